// round 9
// baseline (speedup 1.0000x reference)
#include <cuda_runtime.h>
#include <cuda_fp16.h>
#include <math.h>
#include <math_constants.h>

#define N_NODES 50000
#define N_EDGES 1000000
#define F_IN    30
#define C       64
#define EDIM    11
#define G_GR    1024
#define D_OUT   256
#define NLAYERS 4
#define SCAN_BLKS ((N_NODES + 255) / 256)   // 196

// ---------------- device scratch (static, allocation-free) ----------------
__device__ float    g_feat[N_NODES * C];       // layer input / aggregated output (fp32)
__device__ __half2  g_hwh[N_NODES * (C / 2)];  // h = x @ W, fp16, ch (2l,2l+1) at [row*32+l]
__device__ float    g_res[N_NODES * C];        // x @ Wres + b
__device__ float    g_hs[N_NODES];
__device__ float    g_hd[N_NODES];
__device__ int      g_rowptr[N_NODES + 1];
__device__ int      g_cnt[N_NODES];            // zero-init; returns to 0 every launch
__device__ int4     g_edge4[N_EDGES];          // CSR: {src, half2(et0,et1), half2(et2,et3), pad}
__device__ float    g_aeff[NLAYERS * EDIM];    // We @ ae per layer
__device__ int      g_bsum[SCAN_BLKS];
__device__ int      g_boff[SCAN_BLKS];

// ---------------- packed f32x2 helpers (Blackwell FFMA2 pipe) -------------
__device__ __forceinline__ unsigned long long pack2(float x, float y) {
    unsigned long long r;
    asm("mov.b64 %0, {%1, %2};" : "=l"(r)
        : "r"(__float_as_uint(x)), "r"(__float_as_uint(y)));
    return r;
}
__device__ __forceinline__ void unpack2(unsigned long long v, float& x, float& y) {
    unsigned lo, hi;
    asm("mov.b64 {%0, %1}, %2;" : "=r"(lo), "=r"(hi) : "l"(v));
    x = __uint_as_float(lo); y = __uint_as_float(hi);
}
__device__ __forceinline__ unsigned long long fma2(unsigned long long a,
                                                   unsigned long long b,
                                                   unsigned long long c) {
    unsigned long long d;
    asm("fma.rn.f32x2 %0, %1, %2, %3;" : "=l"(d) : "l"(a), "l"(b), "l"(c));
    return d;
}

// ---------------- init: aeff only (cnt stays 0 by atomicSub invariant) ----
__global__ void k_init(const float* __restrict__ We0, const float* __restrict__ ae0,
                       const float* __restrict__ We,  const float* __restrict__ ae) {
    int i = threadIdx.x;
    if (i < NLAYERS * EDIM) {
        int l = i / EDIM, d = i % EDIM;
        const float* we = (l == 0) ? We0 : (We + (size_t)(l - 1) * EDIM * C);
        const float* av = (l == 0) ? ae0 : (ae + (size_t)(l - 1) * C);
        float s = 0.0f;
        #pragma unroll
        for (int c = 0; c < C; c++) s = fmaf(we[d * C + c], av[c], s);
        g_aeff[i] = s;
    }
}

// ---------------- CSR build ----------------
__global__ void k_hist(const int* __restrict__ edge_index) {
    int e = blockIdx.x * blockDim.x + threadIdx.x;
    if (e >= N_EDGES) return;
    int d = edge_index[N_EDGES + e];
    atomicAdd(&g_cnt[d], 1);
}

__global__ void k_scanA() {
    __shared__ int wsum[8];
    int tid = threadIdx.x, lane = tid & 31, wid = tid >> 5;
    int i = blockIdx.x * 256 + tid;
    int c = (i < N_NODES) ? g_cnt[i] : 0;
    int inc = c;
    #pragma unroll
    for (int o = 1; o < 32; o <<= 1) {
        int t = __shfl_up_sync(0xffffffffu, inc, o);
        if (lane >= o) inc += t;
    }
    if (lane == 31) wsum[wid] = inc;
    __syncthreads();
    if (tid < 8) {
        int v = wsum[tid];
        #pragma unroll
        for (int o = 1; o < 8; o <<= 1) {
            int t = __shfl_up_sync(0x000000ffu, v, o);
            if ((tid & 7) >= o) v += t;
        }
        wsum[tid] = v;
    }
    __syncthreads();
    int excl = (inc - c) + ((wid > 0) ? wsum[wid - 1] : 0);
    if (i < N_NODES) g_rowptr[i] = excl;           // cnt NOT zeroed (scatter sub-to-0)
    if (tid == 255) g_bsum[blockIdx.x] = wsum[7];
}

__global__ void k_scanB() {
    __shared__ int s[256];
    int tid = threadIdx.x;
    s[tid] = (tid < SCAN_BLKS) ? g_bsum[tid] : 0;
    __syncthreads();
    for (int o = 1; o < 256; o <<= 1) {
        int t = (tid >= o) ? s[tid - o] : 0;
        __syncthreads();
        s[tid] += t;
        __syncthreads();
    }
    if (tid < SCAN_BLKS) g_boff[tid] = s[tid] - g_bsum[tid];  // exclusive
    if (tid == 0) g_rowptr[N_NODES] = s[SCAN_BLKS - 1];
}

__global__ void k_scanC() {
    int i = blockIdx.x * 256 + threadIdx.x;
    if (i < N_NODES) g_rowptr[i] += g_boff[blockIdx.x];
}

// ---------------- fused scatter + edge-term: one int4 per edge ------------
// atomicSub drains g_cnt back to 0, preserving the cross-launch invariant.
__global__ void k_scatter_et(const int* __restrict__ edge_index,
                             const float* __restrict__ edge_attr) {
    __shared__ float sa[NLAYERS * EDIM];
    __shared__ float sea[256 * EDIM];
    int tid = threadIdx.x;
    if (tid < NLAYERS * EDIM) sa[tid] = g_aeff[tid];
    int base = blockIdx.x * 256;
    int nE = N_EDGES - base; if (nE > 256) nE = 256;
    for (int i = tid; i < nE * EDIM; i += 256)
        sea[i] = edge_attr[(size_t)base * EDIM + i];
    __syncthreads();
    int e = base + tid;
    if (e >= N_EDGES) return;
    int s = edge_index[e];
    int d = edge_index[N_EDGES + e];
    int old = atomicSub(&g_cnt[d], 1);             // old in [1..deg]
    int pos = g_rowptr[d] + old - 1;
    float ea[EDIM];
    #pragma unroll
    for (int j = 0; j < EDIM; j++) ea[j] = sea[tid * EDIM + j];
    float et[NLAYERS];
    #pragma unroll
    for (int l = 0; l < NLAYERS; l++) {
        float t = 0.0f;
        #pragma unroll
        for (int j = 0; j < EDIM; j++) t = fmaf(ea[j], sa[l * EDIM + j], t);
        et[l] = t;
    }
    __half2 h01 = __floats2half2_rn(et[0], et[1]);
    __half2 h23 = __floats2half2_rn(et[2], et[3]);
    unsigned u01 = *(unsigned*)&h01;
    unsigned u23 = *(unsigned*)&h23;
    g_edge4[pos] = make_int4(s, (int)u01, (int)u23, 0);
}

// ---------------- fused node GEMM via packed f32x2 ------------------------
template <int F, int FS, bool FIRST>
__global__ void k_gemm(const float* __restrict__ xin, const float* __restrict__ W,
                       const float* __restrict__ Wres, const float* __restrict__ asrcv,
                       const float* __restrict__ adstv, const float* __restrict__ bv) {
    __shared__ float Wc[F * 2 * C];   // Wc[k][2c]=W[k,c], Wc[k][2c+1]=Wres[k,c]
    __shared__ float xs[8][4][FS];
    __shared__ float as_[C], ad_[C], bs_[C];
    int tid = threadIdx.x;
    for (int i = tid; i < F * C; i += 256) {
        int k = i / C, c = i % C;
        Wc[k * 2 * C + 2 * c]     = W[i];
        Wc[k * 2 * C + 2 * c + 1] = Wres[i];
    }
    if (tid < C) { as_[tid] = asrcv[tid]; ad_[tid] = adstv[tid]; bs_[tid] = bv[tid]; }
    int lane = tid & 31, wid = tid >> 5;
    int c0 = 2 * lane;
    int row0 = blockIdx.x * 32 + wid * 4;
    #pragma unroll
    for (int r = 0; r < 4; r++) {
        int row = row0 + r;
        if (row < N_NODES) {
            const float* xr = FIRST ? (xin + (size_t)row * F) : (g_feat + (size_t)row * F);
            if (lane < F) xs[wid][r][lane] = xr[lane];
            if (F > 32 && lane + 32 < F) xs[wid][r][lane + 32] = xr[lane + 32];
        }
    }
    __syncthreads();
    unsigned long long A0[4] = {0, 0, 0, 0};   // packed (h, res) for channel c0
    unsigned long long A1[4] = {0, 0, 0, 0};   // packed (h, res) for channel c0+1
    for (int k = 0; k < F; k++) {
        ulonglong2 wp = *(const ulonglong2*)&Wc[k * 2 * C + 4 * lane];
        #pragma unroll
        for (int r = 0; r < 4; r++) {
            float xv = xs[wid][r][k];
            unsigned long long xp = pack2(xv, xv);
            A0[r] = fma2(xp, wp.x, A0[r]);
            A1[r] = fma2(xp, wp.y, A1[r]);
        }
    }
    float2 asv = *(const float2*)&as_[c0];
    float2 adv = *(const float2*)&ad_[c0];
    float2 bsv = *(const float2*)&bs_[c0];
    #pragma unroll
    for (int r = 0; r < 4; r++) {
        int row = row0 + r;
        if (row >= N_NODES) break;
        float h0, r0, h1, r1;
        unpack2(A0[r], h0, r0);
        unpack2(A1[r], h1, r1);
        g_hwh[(size_t)row * 32 + lane] = __floats2half2_rn(h0, h1);
        float2 rv; rv.x = r0 + bsv.x; rv.y = r1 + bsv.y;
        *(float2*)&g_res[(size_t)row * C + c0] = rv;
        float p = h0 * asv.x + h1 * asv.y;
        float q = h0 * adv.x + h1 * adv.y;
        #pragma unroll
        for (int off = 16; off; off >>= 1) {
            p += __shfl_xor_sync(0xffffffffu, p, off);
            q += __shfl_xor_sync(0xffffffffu, q, off);
        }
        if (lane == 0) { g_hs[row] = p; g_hd[row] = q; }
    }
}

// ---------------- per-dst softmax aggregation (no max-shift) --------------
__global__ void k_agg(int layer, int act) {
    int d = blockIdx.x * 8 + (threadIdx.x >> 5);
    if (d >= N_NODES) return;
    int lane = threadIdx.x & 31;
    int beg = g_rowptr[d], end = g_rowptr[d + 1];
    float hdv = g_hd[d];
    float s = 0.0f, acc0 = 0.0f, acc1 = 0.0f;

    for (int base = beg; base < end; base += 32) {
        int p = base + lane;
        bool valid = (p < end);
        int src = 0;
        float pe = 0.0f;
        if (valid) {
            int4 v = g_edge4[p];
            src = v.x;
            unsigned w = (layer & 2) ? (unsigned)v.z : (unsigned)v.y;
            __half2 hh = *(__half2*)&w;
            float etv = (layer & 1) ? __high2float(hh) : __low2float(hh);
            float alpha = g_hs[src] + hdv + etv;
            alpha = (alpha > 0.0f) ? alpha : 0.2f * alpha;   // leaky_relu 0.2
            pe = __expf(alpha);
        }
        s += pe;
        int nval = end - base; if (nval > 32) nval = 32;
        for (int j = 0; j < nval; j++) {
            float pj = __shfl_sync(0xffffffffu, pe, j);
            int   sj = __shfl_sync(0xffffffffu, src, j);
            float2 h = __half22float2(g_hwh[(size_t)sj * 32 + lane]);
            acc0 = fmaf(pj, h.x, acc0);
            acc1 = fmaf(pj, h.y, acc1);
        }
    }
    #pragma unroll
    for (int off = 16; off; off >>= 1)
        s += __shfl_xor_sync(0xffffffffu, s, off);

    float w = 1.0f / (s + 1e-16f);
    size_t o = (size_t)d * C + 2 * lane;
    float2 rv = *(const float2*)&g_res[o];
    float o0 = acc0 * w + rv.x;
    float o1 = acc1 * w + rv.y;
    if (act) {
        o0 = (o0 > 0.0f) ? o0 : 0.01f * o0;
        o1 = (o1 > 0.0f) ? o1 : 0.01f * o1;
    }
    float2 ov; ov.x = o0; ov.y = o1;
    *(float2*)&g_feat[o] = ov;
}

// ---------------- fused pooling + final projection ----------------
__global__ void k_out(const int* __restrict__ batch,
                      const float* __restrict__ Wout, const float* __restrict__ bout,
                      float* __restrict__ out) {
    int g = blockIdx.x;
    int t = threadIdx.x;  // 256 threads
    __shared__ int range[2];
    __shared__ float smx[4][C], ssm[4][C];
    __shared__ float pooled[2 * C];
    if (t == 0) {
        int lo = 0, hi = N_NODES;
        while (lo < hi) { int mid = (lo + hi) >> 1; if (batch[mid] < g) lo = mid + 1; else hi = mid; }
        range[0] = lo;
        lo = range[0]; hi = N_NODES;
        while (lo < hi) { int mid = (lo + hi) >> 1; if (batch[mid] < g + 1) lo = mid + 1; else hi = mid; }
        range[1] = lo;
    }
    __syncthreads();
    int start = range[0], endn = range[1];
    int c = t & 63, q = t >> 6;
    float mx = -CUDART_INF_F, sm = 0.0f;
    for (int n = start + q; n < endn; n += 4) {
        float v = g_feat[(size_t)n * C + c];
        mx = fmaxf(mx, v);
        sm += v;
    }
    smx[q][c] = mx; ssm[q][c] = sm;
    __syncthreads();
    if (t < C) {
        float M = fmaxf(fmaxf(smx[0][t], smx[1][t]), fmaxf(smx[2][t], smx[3][t]));
        float S = ssm[0][t] + ssm[1][t] + ssm[2][t] + ssm[3][t];
        if (!isfinite(M)) M = 0.0f;   // empty graph
        float cnt = (float)(endn - start); if (cnt < 1.0f) cnt = 1.0f;
        float mn = S / cnt;
        pooled[t]     = (M > 0.0f) ? M : 0.01f * M;
        pooled[C + t] = (mn > 0.0f) ? mn : 0.01f * mn;
    }
    __syncthreads();
    float acc = bout[t];
    #pragma unroll
    for (int k = 0; k < 2 * C; k++)
        acc = fmaf(pooled[k], Wout[(size_t)k * D_OUT + t], acc);
    out[(size_t)g * D_OUT + t] = acc;
}

// ---------------- launch (gemm0 moved to position 4 for ncu attribution) --
extern "C" void kernel_launch(void* const* d_in, const int* in_sizes, int n_in,
                              void* d_out, int out_size) {
    const float* x      = (const float*)d_in[0];
    const float* eattr  = (const float*)d_in[1];
    const float* W0     = (const float*)d_in[2];
    const float* asrc0  = (const float*)d_in[3];
    const float* adst0  = (const float*)d_in[4];
    const float* We0    = (const float*)d_in[5];
    const float* ae0    = (const float*)d_in[6];
    const float* Wres0  = (const float*)d_in[7];
    const float* b0     = (const float*)d_in[8];
    const float* W      = (const float*)d_in[9];
    const float* asrc   = (const float*)d_in[10];
    const float* adst   = (const float*)d_in[11];
    const float* We     = (const float*)d_in[12];
    const float* ae     = (const float*)d_in[13];
    const float* Wres   = (const float*)d_in[14];
    const float* b      = (const float*)d_in[15];
    const float* Wout   = (const float*)d_in[16];
    const float* bout   = (const float*)d_in[17];
    const int*   eidx   = (const int*)d_in[18];
    const int*   batch  = (const int*)d_in[19];
    float* out = (float*)d_out;

    const int EB   = (N_EDGES + 255) / 256;
    const int NB8  = (N_NODES + 7) / 8;
    const int NB32 = (N_NODES + 31) / 32;

    k_init<<<1, 64>>>(We0, ae0, We, ae);                         // 1
    k_hist<<<EB, 256>>>(eidx);                                   // 2
    k_scanA<<<SCAN_BLKS, 256>>>();                               // 3
    k_gemm<F_IN, 32, true><<<NB32, 256>>>(x, W0, Wres0,          // 4 <- profiled
                                          asrc0, adst0, b0);
    k_scanB<<<1, 256>>>();                                       // 5
    k_scanC<<<SCAN_BLKS, 256>>>();                               // 6
    k_scatter_et<<<EB, 256>>>(eidx, eattr);                      // 7

    k_agg<<<NB8, 256>>>(0, 1);                                   // 8

    // layers 1..3 (F=64), activation after layers 1,2 only
    for (int i = 0; i < 3; i++) {
        k_gemm<C, C, false><<<NB32, 256>>>(nullptr,
                                           W + (size_t)i * C * C,
                                           Wres + (size_t)i * C * C,
                                           asrc + (size_t)i * C,
                                           adst + (size_t)i * C,
                                           b + (size_t)i * C);
        k_agg<<<NB8, 256>>>(i + 1, (i < 2) ? 1 : 0);
    }

    k_out<<<G_GR, D_OUT>>>(batch, Wout, bout, out);
}

// round 10
// speedup vs baseline: 1.1228x; 1.1228x over previous
#include <cuda_runtime.h>
#include <cuda_fp16.h>
#include <math.h>
#include <math_constants.h>

#define N_NODES 50000
#define N_EDGES 1000000
#define F_IN    30
#define C       64
#define EDIM    11
#define G_GR    1024
#define D_OUT   256
#define NLAYERS 4
#define SCAN_BLKS ((N_NODES + 255) / 256)   // 196 (covers i = N_NODES too)

// ---------------- device scratch (static, allocation-free) ----------------
__device__ float    g_feat[N_NODES * C];       // layer input / aggregated output (fp32)
__device__ __half2  g_hwh[N_NODES * (C / 2)];  // h = x @ W, fp16, ch (2l,2l+1) at [row*32+l]
__device__ float    g_res[N_NODES * C];        // x @ Wres + b
__device__ float    g_hs[N_NODES];
__device__ float    g_hd[N_NODES];
__device__ int      g_rowptr[N_NODES + 1];     // block-LOCAL exclusive scan (add g_boff)
__device__ int      g_cnt[N_NODES];            // zero-init; returns to 0 every launch
__device__ int2     g_edge[NLAYERS * N_EDGES]; // per-layer CSR: (src, et-bits fp32)
__device__ float    g_aeff[NLAYERS * EDIM];    // We @ ae per layer
__device__ int      g_bsum[SCAN_BLKS];
__device__ int      g_boff[SCAN_BLKS];         // exclusive block offsets

// ---------------- packed f32x2 helpers (Blackwell FFMA2 pipe) -------------
__device__ __forceinline__ unsigned long long pack2(float x, float y) {
    unsigned long long r;
    asm("mov.b64 %0, {%1, %2};" : "=l"(r)
        : "r"(__float_as_uint(x)), "r"(__float_as_uint(y)));
    return r;
}
__device__ __forceinline__ void unpack2(unsigned long long v, float& x, float& y) {
    unsigned lo, hi;
    asm("mov.b64 {%0, %1}, %2;" : "=r"(lo), "=r"(hi) : "l"(v));
    x = __uint_as_float(lo); y = __uint_as_float(hi);
}
__device__ __forceinline__ unsigned long long fma2(unsigned long long a,
                                                   unsigned long long b,
                                                   unsigned long long c) {
    unsigned long long d;
    asm("fma.rn.f32x2 %0, %1, %2, %3;" : "=l"(d) : "l"(a), "l"(b), "l"(c));
    return d;
}

// ---------------- hist + aeff (merged) ----------------
__global__ void k_hist(const int* __restrict__ edge_index,
                       const float* __restrict__ We0, const float* __restrict__ ae0,
                       const float* __restrict__ We,  const float* __restrict__ ae) {
    int tid = threadIdx.x;
    if (blockIdx.x == 0 && tid < NLAYERS * EDIM) {
        int l = tid / EDIM, d = tid % EDIM;
        const float* we = (l == 0) ? We0 : (We + (size_t)(l - 1) * EDIM * C);
        const float* av = (l == 0) ? ae0 : (ae + (size_t)(l - 1) * C);
        float s = 0.0f;
        #pragma unroll
        for (int c = 0; c < C; c++) s = fmaf(we[d * C + c], av[c], s);
        g_aeff[tid] = s;
    }
    int e = blockIdx.x * 256 + tid;
    if (e < N_EDGES) atomicAdd(&g_cnt[edge_index[N_EDGES + e]], 1);
}

// block-local exclusive scan of g_cnt -> g_rowptr (incl. i==N), totals -> g_bsum
__global__ void k_scanA() {
    __shared__ int wsum[8];
    int tid = threadIdx.x, lane = tid & 31, wid = tid >> 5;
    int i = blockIdx.x * 256 + tid;
    int c = (i < N_NODES) ? g_cnt[i] : 0;
    int inc = c;
    #pragma unroll
    for (int o = 1; o < 32; o <<= 1) {
        int t = __shfl_up_sync(0xffffffffu, inc, o);
        if (lane >= o) inc += t;
    }
    if (lane == 31) wsum[wid] = inc;
    __syncthreads();
    if (tid < 8) {
        int v = wsum[tid];
        #pragma unroll
        for (int o = 1; o < 8; o <<= 1) {
            int t = __shfl_up_sync(0x000000ffu, v, o);
            if ((tid & 7) >= o) v += t;
        }
        wsum[tid] = v;
    }
    __syncthreads();
    int excl = (inc - c) + ((wid > 0) ? wsum[wid - 1] : 0);
    if (i <= N_NODES) g_rowptr[i] = excl;          // local-exclusive; cnt NOT zeroed
    if (tid == 255) g_bsum[blockIdx.x] = wsum[7];
}

__global__ void k_scanB() {
    __shared__ int s[256];
    int tid = threadIdx.x;
    s[tid] = (tid < SCAN_BLKS) ? g_bsum[tid] : 0;
    __syncthreads();
    for (int o = 1; o < 256; o <<= 1) {
        int t = (tid >= o) ? s[tid - o] : 0;
        __syncthreads();
        s[tid] += t;
        __syncthreads();
    }
    if (tid < SCAN_BLKS) g_boff[tid] = s[tid] - g_bsum[tid];  // exclusive
}

// ---------------- fused scatter + edge-term: (src, et_l) into CSR order ----
// atomicSub drains g_cnt back to 0, preserving the cross-launch invariant.
__global__ void k_scatter_et(const int* __restrict__ edge_index,
                             const float* __restrict__ edge_attr) {
    __shared__ float sa[NLAYERS * EDIM];
    __shared__ float sea[256 * EDIM];
    int tid = threadIdx.x;
    if (tid < NLAYERS * EDIM) sa[tid] = g_aeff[tid];
    int base = blockIdx.x * 256;
    int nE = N_EDGES - base; if (nE > 256) nE = 256;
    for (int i = tid; i < nE * EDIM; i += 256)
        sea[i] = edge_attr[(size_t)base * EDIM + i];
    __syncthreads();
    int e = base + tid;
    if (e >= N_EDGES) return;
    int s = edge_index[e];
    int d = edge_index[N_EDGES + e];
    int old = atomicSub(&g_cnt[d], 1);             // old in [1..deg]
    int pos = g_rowptr[d] + g_boff[d >> 8] + old - 1;
    float ea[EDIM];
    #pragma unroll
    for (int j = 0; j < EDIM; j++) ea[j] = sea[tid * EDIM + j];
    #pragma unroll
    for (int l = 0; l < NLAYERS; l++) {
        float t = 0.0f;
        #pragma unroll
        for (int j = 0; j < EDIM; j++) t = fmaf(ea[j], sa[l * EDIM + j], t);
        g_edge[(size_t)l * N_EDGES + pos] = make_int2(s, __float_as_int(t));
    }
}

// ---------------- fused node GEMM, k-tiled weights (occupancy fix) --------
// Wc stages only KT=32 k-rows of (W,Wres) interleaved -> 16KB smem instead of
// 32KB for F=64, restoring blocks/SM for the latency-bound main loop.
template <int F, int FS, bool FIRST>
__global__ void k_gemm(const float* __restrict__ xin, const float* __restrict__ W,
                       const float* __restrict__ Wres, const float* __restrict__ asrcv,
                       const float* __restrict__ adstv, const float* __restrict__ bv) {
    constexpr int KT = 32;
    __shared__ float Wc[KT * 2 * C];   // 16KB: Wc[k][2c]=W[kt+k,c], Wc[k][2c+1]=Wres[kt+k,c]
    __shared__ float xs[8][4][FS];
    __shared__ float as_[C], ad_[C], bs_[C];
    int tid = threadIdx.x;
    if (tid < C) { as_[tid] = asrcv[tid]; ad_[tid] = adstv[tid]; bs_[tid] = bv[tid]; }
    int lane = tid & 31, wid = tid >> 5;
    int c0 = 2 * lane;
    int row0 = blockIdx.x * 32 + wid * 4;
    #pragma unroll
    for (int r = 0; r < 4; r++) {
        int row = row0 + r;
        if (row < N_NODES) {
            const float* xr = FIRST ? (xin + (size_t)row * F) : (g_feat + (size_t)row * F);
            if (lane < F) xs[wid][r][lane] = xr[lane];
            if (F > 32 && lane + 32 < F) xs[wid][r][lane + 32] = xr[lane + 32];
        }
    }
    unsigned long long A0[4] = {0, 0, 0, 0};   // packed (h, res) for channel c0
    unsigned long long A1[4] = {0, 0, 0, 0};   // packed (h, res) for channel c0+1
    #pragma unroll
    for (int kt = 0; kt < F; kt += KT) {
        const int len = (F - kt < KT) ? (F - kt) : KT;
        __syncthreads();   // first iter: covers xs; later: Wc readers done
        for (int i = tid; i < len * C; i += 256) {
            int k = i / C, c = i % C;
            Wc[k * 2 * C + 2 * c]     = W[(size_t)(kt + k) * C + c];
            Wc[k * 2 * C + 2 * c + 1] = Wres[(size_t)(kt + k) * C + c];
        }
        __syncthreads();
        for (int k = 0; k < len; k++) {
            ulonglong2 wp = *(const ulonglong2*)&Wc[k * 2 * C + 4 * lane];
            #pragma unroll
            for (int r = 0; r < 4; r++) {
                float xv = xs[wid][r][kt + k];
                unsigned long long xp = pack2(xv, xv);
                A0[r] = fma2(xp, wp.x, A0[r]);
                A1[r] = fma2(xp, wp.y, A1[r]);
            }
        }
    }
    float2 asv = *(const float2*)&as_[c0];
    float2 adv = *(const float2*)&ad_[c0];
    float2 bsv = *(const float2*)&bs_[c0];
    #pragma unroll
    for (int r = 0; r < 4; r++) {
        int row = row0 + r;
        if (row >= N_NODES) break;
        float h0, r0, h1, r1;
        unpack2(A0[r], h0, r0);
        unpack2(A1[r], h1, r1);
        g_hwh[(size_t)row * 32 + lane] = __floats2half2_rn(h0, h1);
        float2 rv; rv.x = r0 + bsv.x; rv.y = r1 + bsv.y;
        *(float2*)&g_res[(size_t)row * C + c0] = rv;
        float p = h0 * asv.x + h1 * asv.y;
        float q = h0 * adv.x + h1 * adv.y;
        #pragma unroll
        for (int off = 16; off; off >>= 1) {
            p += __shfl_xor_sync(0xffffffffu, p, off);
            q += __shfl_xor_sync(0xffffffffu, q, off);
        }
        if (lane == 0) { g_hs[row] = p; g_hd[row] = q; }
    }
}

// ---------------- per-dst softmax aggregation (no max-shift) --------------
__global__ void k_agg(int layer, int act) {
    int d = blockIdx.x * 8 + (threadIdx.x >> 5);
    if (d >= N_NODES) return;
    int lane = threadIdx.x & 31;
    int beg = g_rowptr[d] + g_boff[d >> 8];
    int end = g_rowptr[d + 1] + g_boff[(d + 1) >> 8];
    float hdv = g_hd[d];
    const int2* __restrict__ ed = g_edge + (size_t)layer * N_EDGES;
    float s = 0.0f, acc0 = 0.0f, acc1 = 0.0f;

    for (int base = beg; base < end; base += 32) {
        int p = base + lane;
        bool valid = (p < end);
        int src = 0;
        float pe = 0.0f;
        if (valid) {
            int2 v = ed[p];
            src = v.x;
            float alpha = g_hs[src] + hdv + __int_as_float(v.y);
            alpha = (alpha > 0.0f) ? alpha : 0.2f * alpha;   // leaky_relu 0.2
            pe = __expf(alpha);
        }
        s += pe;
        int nval = end - base; if (nval > 32) nval = 32;
        for (int j = 0; j < nval; j++) {
            float pj = __shfl_sync(0xffffffffu, pe, j);
            int   sj = __shfl_sync(0xffffffffu, src, j);
            float2 h = __half22float2(g_hwh[(size_t)sj * 32 + lane]);
            acc0 = fmaf(pj, h.x, acc0);
            acc1 = fmaf(pj, h.y, acc1);
        }
    }
    #pragma unroll
    for (int off = 16; off; off >>= 1)
        s += __shfl_xor_sync(0xffffffffu, s, off);

    float w = 1.0f / (s + 1e-16f);
    size_t o = (size_t)d * C + 2 * lane;
    float2 rv = *(const float2*)&g_res[o];
    float o0 = acc0 * w + rv.x;
    float o1 = acc1 * w + rv.y;
    if (act) {
        o0 = (o0 > 0.0f) ? o0 : 0.01f * o0;
        o1 = (o1 > 0.0f) ? o1 : 0.01f * o1;
    }
    float2 ov; ov.x = o0; ov.y = o1;
    *(float2*)&g_feat[o] = ov;
}

// ---------------- fused pooling + final projection ----------------
__global__ void k_out(const int* __restrict__ batch,
                      const float* __restrict__ Wout, const float* __restrict__ bout,
                      float* __restrict__ out) {
    int g = blockIdx.x;
    int t = threadIdx.x;  // 256 threads
    __shared__ int range[2];
    __shared__ float smx[4][C], ssm[4][C];
    __shared__ float pooled[2 * C];
    if (t == 0) {
        int lo = 0, hi = N_NODES;
        while (lo < hi) { int mid = (lo + hi) >> 1; if (batch[mid] < g) lo = mid + 1; else hi = mid; }
        range[0] = lo;
        lo = range[0]; hi = N_NODES;
        while (lo < hi) { int mid = (lo + hi) >> 1; if (batch[mid] < g + 1) lo = mid + 1; else hi = mid; }
        range[1] = lo;
    }
    __syncthreads();
    int start = range[0], endn = range[1];
    int c = t & 63, q = t >> 6;
    float mx = -CUDART_INF_F, sm = 0.0f;
    for (int n = start + q; n < endn; n += 4) {
        float v = g_feat[(size_t)n * C + c];
        mx = fmaxf(mx, v);
        sm += v;
    }
    smx[q][c] = mx; ssm[q][c] = sm;
    __syncthreads();
    if (t < C) {
        float M = fmaxf(fmaxf(smx[0][t], smx[1][t]), fmaxf(smx[2][t], smx[3][t]));
        float S = ssm[0][t] + ssm[1][t] + ssm[2][t] + ssm[3][t];
        if (!isfinite(M)) M = 0.0f;   // empty graph
        float cnt = (float)(endn - start); if (cnt < 1.0f) cnt = 1.0f;
        float mn = S / cnt;
        pooled[t]     = (M > 0.0f) ? M : 0.01f * M;
        pooled[C + t] = (mn > 0.0f) ? mn : 0.01f * mn;
    }
    __syncthreads();
    float acc = bout[t];
    #pragma unroll
    for (int k = 0; k < 2 * C; k++)
        acc = fmaf(pooled[k], Wout[(size_t)k * D_OUT + t], acc);
    out[(size_t)g * D_OUT + t] = acc;
}

// ---------------- launch ----------------
extern "C" void kernel_launch(void* const* d_in, const int* in_sizes, int n_in,
                              void* d_out, int out_size) {
    const float* x      = (const float*)d_in[0];
    const float* eattr  = (const float*)d_in[1];
    const float* W0     = (const float*)d_in[2];
    const float* asrc0  = (const float*)d_in[3];
    const float* adst0  = (const float*)d_in[4];
    const float* We0    = (const float*)d_in[5];
    const float* ae0    = (const float*)d_in[6];
    const float* Wres0  = (const float*)d_in[7];
    const float* b0     = (const float*)d_in[8];
    const float* W      = (const float*)d_in[9];
    const float* asrc   = (const float*)d_in[10];
    const float* adst   = (const float*)d_in[11];
    const float* We     = (const float*)d_in[12];
    const float* ae     = (const float*)d_in[13];
    const float* Wres   = (const float*)d_in[14];
    const float* b      = (const float*)d_in[15];
    const float* Wout   = (const float*)d_in[16];
    const float* bout   = (const float*)d_in[17];
    const int*   eidx   = (const int*)d_in[18];
    const int*   batch  = (const int*)d_in[19];
    float* out = (float*)d_out;

    const int EB   = (N_EDGES + 255) / 256;
    const int NB8  = (N_NODES + 7) / 8;
    const int NB32 = (N_NODES + 31) / 32;

    k_hist<<<EB, 256>>>(eidx, We0, ae0, We, ae);                 // 1 (hist + aeff)
    k_scanA<<<SCAN_BLKS, 256>>>();                               // 2
    k_scanB<<<1, 256>>>();                                       // 3
    k_gemm<F_IN, 32, true><<<NB32, 256>>>(x, W0, Wres0,          // 4 <- profiled slot
                                          asrc0, adst0, b0);
    k_scatter_et<<<EB, 256>>>(eidx, eattr);                      // 5

    k_agg<<<NB8, 256>>>(0, 1);                                   // 6

    // layers 1..3 (F=64), activation after layers 1,2 only
    for (int i = 0; i < 3; i++) {
        k_gemm<C, C, false><<<NB32, 256>>>(nullptr,
                                           W + (size_t)i * C * C,
                                           Wres + (size_t)i * C * C,
                                           asrc + (size_t)i * C,
                                           adst + (size_t)i * C,
                                           b + (size_t)i * C);
        k_agg<<<NB8, 256>>>(i + 1, (i < 2) ? 1 : 0);
    }

    k_out<<<G_GR, D_OUT>>>(batch, Wout, bout, out);
}

// round 11
// speedup vs baseline: 1.1355x; 1.0113x over previous
#include <cuda_runtime.h>
#include <cuda_fp16.h>
#include <math.h>
#include <math_constants.h>

#define N_NODES 50000
#define N_EDGES 1000000
#define F_IN    30
#define C       64
#define EDIM    11
#define G_GR    1024
#define D_OUT   256
#define NLAYERS 4
#define SCAN_BLKS ((N_NODES + 255) / 256)   // 196 (covers i = N_NODES too)

// ---------------- device scratch (static, allocation-free) ----------------
__device__ float    g_feat[N_NODES * C];       // layer input / aggregated output (fp32)
__device__ __half2  g_hwh[N_NODES * (C / 2)];  // h = x @ W, fp16, ch (2l,2l+1) at [row*32+l]
__device__ float    g_res[N_NODES * C];        // x @ Wres + b
__device__ float    g_hs[N_NODES];
__device__ float    g_hd[N_NODES];
__device__ int      g_rowptr[N_NODES + 1];     // block-LOCAL exclusive scan (add g_boff)
__device__ int      g_cnt[N_NODES];            // zero-init; returns to 0 every launch
__device__ int2     g_edge[NLAYERS * N_EDGES]; // per-layer CSR: (src, et-bits fp32)
__device__ float    g_aeff[NLAYERS * EDIM];    // We @ ae per layer
__device__ int      g_bsum[SCAN_BLKS];
__device__ int      g_boff[SCAN_BLKS];         // exclusive block offsets

// ---------------- packed f32x2 helpers (Blackwell FFMA2 pipe) -------------
__device__ __forceinline__ unsigned long long pack2(float x, float y) {
    unsigned long long r;
    asm("mov.b64 %0, {%1, %2};" : "=l"(r)
        : "r"(__float_as_uint(x)), "r"(__float_as_uint(y)));
    return r;
}
__device__ __forceinline__ void unpack2(unsigned long long v, float& x, float& y) {
    unsigned lo, hi;
    asm("mov.b64 {%0, %1}, %2;" : "=r"(lo), "=r"(hi) : "l"(v));
    x = __uint_as_float(lo); y = __uint_as_float(hi);
}
__device__ __forceinline__ unsigned long long fma2(unsigned long long a,
                                                   unsigned long long b,
                                                   unsigned long long c) {
    unsigned long long d;
    asm("fma.rn.f32x2 %0, %1, %2, %3;" : "=l"(d) : "l"(a), "l"(b), "l"(c));
    return d;
}

// ---------------- hist + aeff (merged) ----------------
__global__ void k_hist(const int* __restrict__ edge_index,
                       const float* __restrict__ We0, const float* __restrict__ ae0,
                       const float* __restrict__ We,  const float* __restrict__ ae) {
    int tid = threadIdx.x;
    if (blockIdx.x == 0 && tid < NLAYERS * EDIM) {
        int l = tid / EDIM, d = tid % EDIM;
        const float* we = (l == 0) ? We0 : (We + (size_t)(l - 1) * EDIM * C);
        const float* av = (l == 0) ? ae0 : (ae + (size_t)(l - 1) * C);
        float s = 0.0f;
        #pragma unroll
        for (int c = 0; c < C; c++) s = fmaf(we[d * C + c], av[c], s);
        g_aeff[tid] = s;
    }
    int e = blockIdx.x * 256 + tid;
    if (e < N_EDGES) atomicAdd(&g_cnt[edge_index[N_EDGES + e]], 1);
}

// block-local exclusive scan of g_cnt -> g_rowptr (incl. i==N), totals -> g_bsum
__global__ void k_scanA() {
    __shared__ int wsum[8];
    int tid = threadIdx.x, lane = tid & 31, wid = tid >> 5;
    int i = blockIdx.x * 256 + tid;
    int c = (i < N_NODES) ? g_cnt[i] : 0;
    int inc = c;
    #pragma unroll
    for (int o = 1; o < 32; o <<= 1) {
        int t = __shfl_up_sync(0xffffffffu, inc, o);
        if (lane >= o) inc += t;
    }
    if (lane == 31) wsum[wid] = inc;
    __syncthreads();
    if (tid < 8) {
        int v = wsum[tid];
        #pragma unroll
        for (int o = 1; o < 8; o <<= 1) {
            int t = __shfl_up_sync(0x000000ffu, v, o);
            if ((tid & 7) >= o) v += t;
        }
        wsum[tid] = v;
    }
    __syncthreads();
    int excl = (inc - c) + ((wid > 0) ? wsum[wid - 1] : 0);
    if (i <= N_NODES) g_rowptr[i] = excl;          // local-exclusive; cnt NOT zeroed
    if (tid == 255) g_bsum[blockIdx.x] = wsum[7];
}

__global__ void k_scanB() {
    __shared__ int s[256];
    int tid = threadIdx.x;
    s[tid] = (tid < SCAN_BLKS) ? g_bsum[tid] : 0;
    __syncthreads();
    for (int o = 1; o < 256; o <<= 1) {
        int t = (tid >= o) ? s[tid - o] : 0;
        __syncthreads();
        s[tid] += t;
        __syncthreads();
    }
    if (tid < SCAN_BLKS) g_boff[tid] = s[tid] - g_bsum[tid];  // exclusive
}

// ---------------- fused scatter + edge-term: (src, et_l) into CSR order ----
// atomicSub drains g_cnt back to 0, preserving the cross-launch invariant.
__global__ void k_scatter_et(const int* __restrict__ edge_index,
                             const float* __restrict__ edge_attr) {
    __shared__ float sa[NLAYERS * EDIM];
    __shared__ float sea[256 * EDIM];
    int tid = threadIdx.x;
    if (tid < NLAYERS * EDIM) sa[tid] = g_aeff[tid];
    int base = blockIdx.x * 256;
    int nE = N_EDGES - base; if (nE > 256) nE = 256;
    for (int i = tid; i < nE * EDIM; i += 256)
        sea[i] = edge_attr[(size_t)base * EDIM + i];
    __syncthreads();
    int e = base + tid;
    if (e >= N_EDGES) return;
    int s = edge_index[e];
    int d = edge_index[N_EDGES + e];
    int old = atomicSub(&g_cnt[d], 1);             // old in [1..deg]
    int pos = g_rowptr[d] + g_boff[d >> 8] + old - 1;
    float ea[EDIM];
    #pragma unroll
    for (int j = 0; j < EDIM; j++) ea[j] = sea[tid * EDIM + j];
    #pragma unroll
    for (int l = 0; l < NLAYERS; l++) {
        float t = 0.0f;
        #pragma unroll
        for (int j = 0; j < EDIM; j++) t = fmaf(ea[j], sa[l * EDIM + j], t);
        g_edge[(size_t)l * N_EDGES + pos] = make_int2(s, __float_as_int(t));
    }
}

// ---------------- fused node GEMM, k-tiled weights ------------------------
// __launch_bounds__(256,5): cap regs ~51 so 5 blocks/SM fit the 64K regfile
// (was 54 regs -> 4 blocks; occupancy, not smem, was the residency cap).
template <int F, int FS, bool FIRST>
__global__ void __launch_bounds__(256, 5)
k_gemm(const float* __restrict__ xin, const float* __restrict__ W,
       const float* __restrict__ Wres, const float* __restrict__ asrcv,
       const float* __restrict__ adstv, const float* __restrict__ bv) {
    constexpr int KT = 32;
    __shared__ float Wc[KT * 2 * C];   // 16KB: Wc[k][2c]=W[kt+k,c], Wc[k][2c+1]=Wres[kt+k,c]
    __shared__ float xs[8][4][FS];
    __shared__ float as_[C], ad_[C], bs_[C];
    int tid = threadIdx.x;
    if (tid < C) { as_[tid] = asrcv[tid]; ad_[tid] = adstv[tid]; bs_[tid] = bv[tid]; }
    int lane = tid & 31, wid = tid >> 5;
    int c0 = 2 * lane;
    int row0 = blockIdx.x * 32 + wid * 4;
    #pragma unroll
    for (int r = 0; r < 4; r++) {
        int row = row0 + r;
        if (row < N_NODES) {
            const float* xr = FIRST ? (xin + (size_t)row * F) : (g_feat + (size_t)row * F);
            if (lane < F) xs[wid][r][lane] = xr[lane];
            if (F > 32 && lane + 32 < F) xs[wid][r][lane + 32] = xr[lane + 32];
        }
    }
    unsigned long long A0[4] = {0, 0, 0, 0};   // packed (h, res) for channel c0
    unsigned long long A1[4] = {0, 0, 0, 0};   // packed (h, res) for channel c0+1
    #pragma unroll
    for (int kt = 0; kt < F; kt += KT) {
        const int len = (F - kt < KT) ? (F - kt) : KT;
        __syncthreads();   // first iter: covers xs; later: Wc readers done
        for (int i = tid; i < len * C; i += 256) {
            int k = i / C, c = i % C;
            Wc[k * 2 * C + 2 * c]     = W[(size_t)(kt + k) * C + c];
            Wc[k * 2 * C + 2 * c + 1] = Wres[(size_t)(kt + k) * C + c];
        }
        __syncthreads();
        for (int k = 0; k < len; k++) {
            ulonglong2 wp = *(const ulonglong2*)&Wc[k * 2 * C + 4 * lane];
            #pragma unroll
            for (int r = 0; r < 4; r++) {
                float xv = xs[wid][r][kt + k];
                unsigned long long xp = pack2(xv, xv);
                A0[r] = fma2(xp, wp.x, A0[r]);
                A1[r] = fma2(xp, wp.y, A1[r]);
            }
        }
    }
    float2 asv = *(const float2*)&as_[c0];
    float2 adv = *(const float2*)&ad_[c0];
    float2 bsv = *(const float2*)&bs_[c0];
    #pragma unroll
    for (int r = 0; r < 4; r++) {
        int row = row0 + r;
        if (row >= N_NODES) break;
        float h0, r0, h1, r1;
        unpack2(A0[r], h0, r0);
        unpack2(A1[r], h1, r1);
        g_hwh[(size_t)row * 32 + lane] = __floats2half2_rn(h0, h1);
        float2 rv; rv.x = r0 + bsv.x; rv.y = r1 + bsv.y;
        *(float2*)&g_res[(size_t)row * C + c0] = rv;
        float p = h0 * asv.x + h1 * asv.y;
        float q = h0 * adv.x + h1 * adv.y;
        #pragma unroll
        for (int off = 16; off; off >>= 1) {
            p += __shfl_xor_sync(0xffffffffu, p, off);
            q += __shfl_xor_sync(0xffffffffu, q, off);
        }
        if (lane == 0) { g_hs[row] = p; g_hd[row] = q; }
    }
}

// ---------------- per-dst softmax aggregation (no max-shift) --------------
__global__ void k_agg(int layer, int act) {
    int d = blockIdx.x * 8 + (threadIdx.x >> 5);
    if (d >= N_NODES) return;
    int lane = threadIdx.x & 31;
    int beg = g_rowptr[d] + g_boff[d >> 8];
    int end = g_rowptr[d + 1] + g_boff[(d + 1) >> 8];
    float hdv = g_hd[d];
    const int2* __restrict__ ed = g_edge + (size_t)layer * N_EDGES;
    float s = 0.0f, acc0 = 0.0f, acc1 = 0.0f;

    for (int base = beg; base < end; base += 32) {
        int p = base + lane;
        bool valid = (p < end);
        int src = 0;
        float pe = 0.0f;
        if (valid) {
            int2 v = ed[p];
            src = v.x;
            float alpha = g_hs[src] + hdv + __int_as_float(v.y);
            alpha = (alpha > 0.0f) ? alpha : 0.2f * alpha;   // leaky_relu 0.2
            pe = __expf(alpha);
        }
        s += pe;
        int nval = end - base; if (nval > 32) nval = 32;
        for (int j = 0; j < nval; j++) {
            float pj = __shfl_sync(0xffffffffu, pe, j);
            int   sj = __shfl_sync(0xffffffffu, src, j);
            float2 h = __half22float2(g_hwh[(size_t)sj * 32 + lane]);
            acc0 = fmaf(pj, h.x, acc0);
            acc1 = fmaf(pj, h.y, acc1);
        }
    }
    #pragma unroll
    for (int off = 16; off; off >>= 1)
        s += __shfl_xor_sync(0xffffffffu, s, off);

    float w = 1.0f / (s + 1e-16f);
    size_t o = (size_t)d * C + 2 * lane;
    float2 rv = *(const float2*)&g_res[o];
    float o0 = acc0 * w + rv.x;
    float o1 = acc1 * w + rv.y;
    if (act) {
        o0 = (o0 > 0.0f) ? o0 : 0.01f * o0;
        o1 = (o1 > 0.0f) ? o1 : 0.01f * o1;
    }
    float2 ov; ov.x = o0; ov.y = o1;
    *(float2*)&g_feat[o] = ov;
}

// ---------------- fused pooling + final projection ----------------
__global__ void k_out(const int* __restrict__ batch,
                      const float* __restrict__ Wout, const float* __restrict__ bout,
                      float* __restrict__ out) {
    int g = blockIdx.x;
    int t = threadIdx.x;  // 256 threads
    __shared__ int range[2];
    __shared__ float smx[4][C], ssm[4][C];
    __shared__ float pooled[2 * C];
    if (t == 0) {
        int lo = 0, hi = N_NODES;
        while (lo < hi) { int mid = (lo + hi) >> 1; if (batch[mid] < g) lo = mid + 1; else hi = mid; }
        range[0] = lo;
        lo = range[0]; hi = N_NODES;
        while (lo < hi) { int mid = (lo + hi) >> 1; if (batch[mid] < g + 1) lo = mid + 1; else hi = mid; }
        range[1] = lo;
    }
    __syncthreads();
    int start = range[0], endn = range[1];
    int c = t & 63, q = t >> 6;
    float mx = -CUDART_INF_F, sm = 0.0f;
    for (int n = start + q; n < endn; n += 4) {
        float v = g_feat[(size_t)n * C + c];
        mx = fmaxf(mx, v);
        sm += v;
    }
    smx[q][c] = mx; ssm[q][c] = sm;
    __syncthreads();
    if (t < C) {
        float M = fmaxf(fmaxf(smx[0][t], smx[1][t]), fmaxf(smx[2][t], smx[3][t]));
        float S = ssm[0][t] + ssm[1][t] + ssm[2][t] + ssm[3][t];
        if (!isfinite(M)) M = 0.0f;   // empty graph
        float cnt = (float)(endn - start); if (cnt < 1.0f) cnt = 1.0f;
        float mn = S / cnt;
        pooled[t]     = (M > 0.0f) ? M : 0.01f * M;
        pooled[C + t] = (mn > 0.0f) ? mn : 0.01f * mn;
    }
    __syncthreads();
    float acc = bout[t];
    #pragma unroll
    for (int k = 0; k < 2 * C; k++)
        acc = fmaf(pooled[k], Wout[(size_t)k * D_OUT + t], acc);
    out[(size_t)g * D_OUT + t] = acc;
}

// ---------------- launch (scatter_et in profiled slot 4) ------------------
extern "C" void kernel_launch(void* const* d_in, const int* in_sizes, int n_in,
                              void* d_out, int out_size) {
    const float* x      = (const float*)d_in[0];
    const float* eattr  = (const float*)d_in[1];
    const float* W0     = (const float*)d_in[2];
    const float* asrc0  = (const float*)d_in[3];
    const float* adst0  = (const float*)d_in[4];
    const float* We0    = (const float*)d_in[5];
    const float* ae0    = (const float*)d_in[6];
    const float* Wres0  = (const float*)d_in[7];
    const float* b0     = (const float*)d_in[8];
    const float* W      = (const float*)d_in[9];
    const float* asrc   = (const float*)d_in[10];
    const float* adst   = (const float*)d_in[11];
    const float* We     = (const float*)d_in[12];
    const float* ae     = (const float*)d_in[13];
    const float* Wres   = (const float*)d_in[14];
    const float* b      = (const float*)d_in[15];
    const float* Wout   = (const float*)d_in[16];
    const float* bout   = (const float*)d_in[17];
    const int*   eidx   = (const int*)d_in[18];
    const int*   batch  = (const int*)d_in[19];
    float* out = (float*)d_out;

    const int EB   = (N_EDGES + 255) / 256;
    const int NB8  = (N_NODES + 7) / 8;
    const int NB32 = (N_NODES + 31) / 32;

    k_hist<<<EB, 256>>>(eidx, We0, ae0, We, ae);                 // 1 (hist + aeff)
    k_scanA<<<SCAN_BLKS, 256>>>();                               // 2
    k_scanB<<<1, 256>>>();                                       // 3
    k_scatter_et<<<EB, 256>>>(eidx, eattr);                      // 4 <- profiled slot
    k_gemm<F_IN, 32, true><<<NB32, 256>>>(x, W0, Wres0,          // 5
                                          asrc0, adst0, b0);

    k_agg<<<NB8, 256>>>(0, 1);                                   // 6

    // layers 1..3 (F=64), activation after layers 1,2 only
    for (int i = 0; i < 3; i++) {
        k_gemm<C, C, false><<<NB32, 256>>>(nullptr,
                                           W + (size_t)i * C * C,
                                           Wres + (size_t)i * C * C,
                                           asrc + (size_t)i * C,
                                           adst + (size_t)i * C,
                                           b + (size_t)i * C);
        k_agg<<<NB8, 256>>>(i + 1, (i < 2) ? 1 : 0);
    }

    k_out<<<G_GR, D_OUT>>>(batch, Wout, bout, out);
}

// round 12
// speedup vs baseline: 1.1772x; 1.0368x over previous
#include <cuda_runtime.h>
#include <cuda_fp16.h>
#include <math.h>
#include <math_constants.h>

#define N_NODES 50000
#define N_EDGES 1000000
#define F_IN    30
#define C       64
#define EDIM    11
#define G_GR    1024
#define D_OUT   256
#define NLAYERS 4
#define SCAN_BLKS ((N_NODES + 255) / 256)   // 196 (covers i = N_NODES too)

// ---------------- device scratch (static, allocation-free) ----------------
__device__ float    g_feat[N_NODES * C];       // layer input / aggregated output (fp32)
__device__ __half2  g_hwh[N_NODES * (C / 2)];  // h = x @ W, fp16, ch (2l,2l+1) at [row*32+l]
__device__ float    g_res[N_NODES * C];        // x @ Wres + b
__device__ float    g_hs[N_NODES];
__device__ float    g_hd[N_NODES];
__device__ int      g_rowptr[N_NODES + 1];     // block-LOCAL exclusive scan (add g_boff)
__device__ int      g_cnt[N_NODES];            // zero-init; returns to 0 every launch
__device__ int4     g_edge4[N_EDGES];          // CSR: {src, h2(et0,et1), src, h2(et2,et3)}
__device__ float    g_aeff[NLAYERS * EDIM];    // We @ ae per layer
__device__ int      g_bsum[SCAN_BLKS];
__device__ int      g_boff[SCAN_BLKS];         // exclusive block offsets

// ---------------- packed f32x2 helpers (Blackwell FFMA2 pipe) -------------
__device__ __forceinline__ unsigned long long pack2(float x, float y) {
    unsigned long long r;
    asm("mov.b64 %0, {%1, %2};" : "=l"(r)
        : "r"(__float_as_uint(x)), "r"(__float_as_uint(y)));
    return r;
}
__device__ __forceinline__ void unpack2(unsigned long long v, float& x, float& y) {
    unsigned lo, hi;
    asm("mov.b64 {%0, %1}, %2;" : "=r"(lo), "=r"(hi) : "l"(v));
    x = __uint_as_float(lo); y = __uint_as_float(hi);
}
__device__ __forceinline__ unsigned long long fma2(unsigned long long a,
                                                   unsigned long long b,
                                                   unsigned long long c) {
    unsigned long long d;
    asm("fma.rn.f32x2 %0, %1, %2, %3;" : "=l"(d) : "l"(a), "l"(b), "l"(c));
    return d;
}

// ---------------- hist + aeff (merged) ----------------
__global__ void k_hist(const int* __restrict__ edge_index,
                       const float* __restrict__ We0, const float* __restrict__ ae0,
                       const float* __restrict__ We,  const float* __restrict__ ae) {
    int tid = threadIdx.x;
    if (blockIdx.x == 0 && tid < NLAYERS * EDIM) {
        int l = tid / EDIM, d = tid % EDIM;
        const float* we = (l == 0) ? We0 : (We + (size_t)(l - 1) * EDIM * C);
        const float* av = (l == 0) ? ae0 : (ae + (size_t)(l - 1) * C);
        float s = 0.0f;
        #pragma unroll
        for (int c = 0; c < C; c++) s = fmaf(we[d * C + c], av[c], s);
        g_aeff[tid] = s;
    }
    int e = blockIdx.x * 256 + tid;
    if (e < N_EDGES) atomicAdd(&g_cnt[edge_index[N_EDGES + e]], 1);
}

// block-local exclusive scan of g_cnt -> g_rowptr (incl. i==N), totals -> g_bsum
__global__ void k_scanA() {
    __shared__ int wsum[8];
    int tid = threadIdx.x, lane = tid & 31, wid = tid >> 5;
    int i = blockIdx.x * 256 + tid;
    int c = (i < N_NODES) ? g_cnt[i] : 0;
    int inc = c;
    #pragma unroll
    for (int o = 1; o < 32; o <<= 1) {
        int t = __shfl_up_sync(0xffffffffu, inc, o);
        if (lane >= o) inc += t;
    }
    if (lane == 31) wsum[wid] = inc;
    __syncthreads();
    if (tid < 8) {
        int v = wsum[tid];
        #pragma unroll
        for (int o = 1; o < 8; o <<= 1) {
            int t = __shfl_up_sync(0x000000ffu, v, o);
            if ((tid & 7) >= o) v += t;
        }
        wsum[tid] = v;
    }
    __syncthreads();
    int excl = (inc - c) + ((wid > 0) ? wsum[wid - 1] : 0);
    if (i <= N_NODES) g_rowptr[i] = excl;          // local-exclusive; cnt NOT zeroed
    if (tid == 255) g_bsum[blockIdx.x] = wsum[7];
}

__global__ void k_scanB() {
    __shared__ int s[256];
    int tid = threadIdx.x;
    s[tid] = (tid < SCAN_BLKS) ? g_bsum[tid] : 0;
    __syncthreads();
    for (int o = 1; o < 256; o <<= 1) {
        int t = (tid >= o) ? s[tid - o] : 0;
        __syncthreads();
        s[tid] += t;
        __syncthreads();
    }
    if (tid < SCAN_BLKS) g_boff[tid] = s[tid] - g_bsum[tid];  // exclusive
}

// ---------------- fused scatter + edge-term: ONE int4 store per edge ------
// Payload duplicates src so agg reads a single 8B int2 per edge per layer:
//   int2 #0 = (src, half2(et0,et1)),  int2 #1 = (src, half2(et2,et3)).
// One scattered <=32B store costs one L2 sector: 32MB total vs 128MB for
// the 4-array version measured at 58.9us.
__global__ void k_scatter_et(const int* __restrict__ edge_index,
                             const float* __restrict__ edge_attr) {
    __shared__ float sa[NLAYERS * EDIM];
    __shared__ float sea[256 * EDIM];
    int tid = threadIdx.x;
    if (tid < NLAYERS * EDIM) sa[tid] = g_aeff[tid];
    int base = blockIdx.x * 256;
    int nE = N_EDGES - base; if (nE > 256) nE = 256;
    for (int i = tid; i < nE * EDIM; i += 256)
        sea[i] = edge_attr[(size_t)base * EDIM + i];
    __syncthreads();
    int e = base + tid;
    if (e >= N_EDGES) return;
    int s = edge_index[e];
    int d = edge_index[N_EDGES + e];
    int old = atomicSub(&g_cnt[d], 1);             // old in [1..deg]
    int pos = g_rowptr[d] + g_boff[d >> 8] + old - 1;
    float ea[EDIM];
    #pragma unroll
    for (int j = 0; j < EDIM; j++) ea[j] = sea[tid * EDIM + j];
    float et[NLAYERS];
    #pragma unroll
    for (int l = 0; l < NLAYERS; l++) {
        float t = 0.0f;
        #pragma unroll
        for (int j = 0; j < EDIM; j++) t = fmaf(ea[j], sa[l * EDIM + j], t);
        et[l] = t;
    }
    __half2 h01 = __floats2half2_rn(et[0], et[1]);
    __half2 h23 = __floats2half2_rn(et[2], et[3]);
    g_edge4[pos] = make_int4(s, (int)*(unsigned*)&h01, s, (int)*(unsigned*)&h23);
}

// ---------------- fused node GEMM, k-tiled weights ------------------------
template <int F, int FS, bool FIRST>
__global__ void __launch_bounds__(256, 5)
k_gemm(const float* __restrict__ xin, const float* __restrict__ W,
       const float* __restrict__ Wres, const float* __restrict__ asrcv,
       const float* __restrict__ adstv, const float* __restrict__ bv) {
    constexpr int KT = 32;
    __shared__ float Wc[KT * 2 * C];   // 16KB staged (W,Wres) interleaved
    __shared__ float xs[8][4][FS];
    __shared__ float as_[C], ad_[C], bs_[C];
    int tid = threadIdx.x;
    if (tid < C) { as_[tid] = asrcv[tid]; ad_[tid] = adstv[tid]; bs_[tid] = bv[tid]; }
    int lane = tid & 31, wid = tid >> 5;
    int c0 = 2 * lane;
    int row0 = blockIdx.x * 32 + wid * 4;
    #pragma unroll
    for (int r = 0; r < 4; r++) {
        int row = row0 + r;
        if (row < N_NODES) {
            const float* xr = FIRST ? (xin + (size_t)row * F) : (g_feat + (size_t)row * F);
            if (lane < F) xs[wid][r][lane] = xr[lane];
            if (F > 32 && lane + 32 < F) xs[wid][r][lane + 32] = xr[lane + 32];
        }
    }
    unsigned long long A0[4] = {0, 0, 0, 0};   // packed (h, res) for channel c0
    unsigned long long A1[4] = {0, 0, 0, 0};   // packed (h, res) for channel c0+1
    #pragma unroll
    for (int kt = 0; kt < F; kt += KT) {
        const int len = (F - kt < KT) ? (F - kt) : KT;
        __syncthreads();   // first iter: covers xs; later: Wc readers done
        for (int i = tid; i < len * C; i += 256) {
            int k = i / C, c = i % C;
            Wc[k * 2 * C + 2 * c]     = W[(size_t)(kt + k) * C + c];
            Wc[k * 2 * C + 2 * c + 1] = Wres[(size_t)(kt + k) * C + c];
        }
        __syncthreads();
        for (int k = 0; k < len; k++) {
            ulonglong2 wp = *(const ulonglong2*)&Wc[k * 2 * C + 4 * lane];
            #pragma unroll
            for (int r = 0; r < 4; r++) {
                float xv = xs[wid][r][kt + k];
                unsigned long long xp = pack2(xv, xv);
                A0[r] = fma2(xp, wp.x, A0[r]);
                A1[r] = fma2(xp, wp.y, A1[r]);
            }
        }
    }
    float2 asv = *(const float2*)&as_[c0];
    float2 adv = *(const float2*)&ad_[c0];
    float2 bsv = *(const float2*)&bs_[c0];
    #pragma unroll
    for (int r = 0; r < 4; r++) {
        int row = row0 + r;
        if (row >= N_NODES) break;
        float h0, r0, h1, r1;
        unpack2(A0[r], h0, r0);
        unpack2(A1[r], h1, r1);
        g_hwh[(size_t)row * 32 + lane] = __floats2half2_rn(h0, h1);
        float2 rv; rv.x = r0 + bsv.x; rv.y = r1 + bsv.y;
        *(float2*)&g_res[(size_t)row * C + c0] = rv;
        float p = h0 * asv.x + h1 * asv.y;
        float q = h0 * adv.x + h1 * adv.y;
        #pragma unroll
        for (int off = 16; off; off >>= 1) {
            p += __shfl_xor_sync(0xffffffffu, p, off);
            q += __shfl_xor_sync(0xffffffffu, q, off);
        }
        if (lane == 0) { g_hs[row] = p; g_hd[row] = q; }
    }
}

// ---------------- per-dst softmax aggregation (no max-shift) --------------
__global__ void k_agg(int layer, int act) {
    int d = blockIdx.x * 8 + (threadIdx.x >> 5);
    if (d >= N_NODES) return;
    int lane = threadIdx.x & 31;
    int beg = g_rowptr[d] + g_boff[d >> 8];
    int end = g_rowptr[d + 1] + g_boff[(d + 1) >> 8];
    float hdv = g_hd[d];
    const int2* __restrict__ ed2 = (const int2*)g_edge4;
    const int half_sel = layer >> 1;        // which int2 of the int4
    const bool hi_sel  = (layer & 1) != 0;  // which half of the half2
    float s = 0.0f, acc0 = 0.0f, acc1 = 0.0f;

    for (int base = beg; base < end; base += 32) {
        int p = base + lane;
        bool valid = (p < end);
        int src = 0;
        float pe = 0.0f;
        if (valid) {
            int2 v = ed2[2 * (size_t)p + half_sel];
            src = v.x;
            __half2 hh = *(__half2*)&v.y;
            float etv = hi_sel ? __high2float(hh) : __low2float(hh);
            float alpha = g_hs[src] + hdv + etv;
            alpha = (alpha > 0.0f) ? alpha : 0.2f * alpha;   // leaky_relu 0.2
            pe = __expf(alpha);
        }
        s += pe;
        int nval = end - base; if (nval > 32) nval = 32;
        for (int j = 0; j < nval; j++) {
            float pj = __shfl_sync(0xffffffffu, pe, j);
            int   sj = __shfl_sync(0xffffffffu, src, j);
            float2 h = __half22float2(g_hwh[(size_t)sj * 32 + lane]);
            acc0 = fmaf(pj, h.x, acc0);
            acc1 = fmaf(pj, h.y, acc1);
        }
    }
    #pragma unroll
    for (int off = 16; off; off >>= 1)
        s += __shfl_xor_sync(0xffffffffu, s, off);

    float w = 1.0f / (s + 1e-16f);
    size_t o = (size_t)d * C + 2 * lane;
    float2 rv = *(const float2*)&g_res[o];
    float o0 = acc0 * w + rv.x;
    float o1 = acc1 * w + rv.y;
    if (act) {
        o0 = (o0 > 0.0f) ? o0 : 0.01f * o0;
        o1 = (o1 > 0.0f) ? o1 : 0.01f * o1;
    }
    float2 ov; ov.x = o0; ov.y = o1;
    *(float2*)&g_feat[o] = ov;
}

// ---------------- fused pooling + final projection ----------------
__global__ void k_out(const int* __restrict__ batch,
                      const float* __restrict__ Wout, const float* __restrict__ bout,
                      float* __restrict__ out) {
    int g = blockIdx.x;
    int t = threadIdx.x;  // 256 threads
    __shared__ int range[2];
    __shared__ float smx[4][C], ssm[4][C];
    __shared__ float pooled[2 * C];
    if (t == 0) {
        int lo = 0, hi = N_NODES;
        while (lo < hi) { int mid = (lo + hi) >> 1; if (batch[mid] < g) lo = mid + 1; else hi = mid; }
        range[0] = lo;
        lo = range[0]; hi = N_NODES;
        while (lo < hi) { int mid = (lo + hi) >> 1; if (batch[mid] < g + 1) lo = mid + 1; else hi = mid; }
        range[1] = lo;
    }
    __syncthreads();
    int start = range[0], endn = range[1];
    int c = t & 63, q = t >> 6;
    float mx = -CUDART_INF_F, sm = 0.0f;
    for (int n = start + q; n < endn; n += 4) {
        float v = g_feat[(size_t)n * C + c];
        mx = fmaxf(mx, v);
        sm += v;
    }
    smx[q][c] = mx; ssm[q][c] = sm;
    __syncthreads();
    if (t < C) {
        float M = fmaxf(fmaxf(smx[0][t], smx[1][t]), fmaxf(smx[2][t], smx[3][t]));
        float S = ssm[0][t] + ssm[1][t] + ssm[2][t] + ssm[3][t];
        if (!isfinite(M)) M = 0.0f;   // empty graph
        float cnt = (float)(endn - start); if (cnt < 1.0f) cnt = 1.0f;
        float mn = S / cnt;
        pooled[t]     = (M > 0.0f) ? M : 0.01f * M;
        pooled[C + t] = (mn > 0.0f) ? mn : 0.01f * mn;
    }
    __syncthreads();
    float acc = bout[t];
    #pragma unroll
    for (int k = 0; k < 2 * C; k++)
        acc = fmaf(pooled[k], Wout[(size_t)k * D_OUT + t], acc);
    out[(size_t)g * D_OUT + t] = acc;
}

// ---------------- launch (scatter_et in profiled slot 4) ------------------
extern "C" void kernel_launch(void* const* d_in, const int* in_sizes, int n_in,
                              void* d_out, int out_size) {
    const float* x      = (const float*)d_in[0];
    const float* eattr  = (const float*)d_in[1];
    const float* W0     = (const float*)d_in[2];
    const float* asrc0  = (const float*)d_in[3];
    const float* adst0  = (const float*)d_in[4];
    const float* We0    = (const float*)d_in[5];
    const float* ae0    = (const float*)d_in[6];
    const float* Wres0  = (const float*)d_in[7];
    const float* b0     = (const float*)d_in[8];
    const float* W      = (const float*)d_in[9];
    const float* asrc   = (const float*)d_in[10];
    const float* adst   = (const float*)d_in[11];
    const float* We     = (const float*)d_in[12];
    const float* ae     = (const float*)d_in[13];
    const float* Wres   = (const float*)d_in[14];
    const float* b      = (const float*)d_in[15];
    const float* Wout   = (const float*)d_in[16];
    const float* bout   = (const float*)d_in[17];
    const int*   eidx   = (const int*)d_in[18];
    const int*   batch  = (const int*)d_in[19];
    float* out = (float*)d_out;

    const int EB   = (N_EDGES + 255) / 256;
    const int NB8  = (N_NODES + 7) / 8;
    const int NB32 = (N_NODES + 31) / 32;

    k_hist<<<EB, 256>>>(eidx, We0, ae0, We, ae);                 // 1 (hist + aeff)
    k_scanA<<<SCAN_BLKS, 256>>>();                               // 2
    k_scanB<<<1, 256>>>();                                       // 3
    k_scatter_et<<<EB, 256>>>(eidx, eattr);                      // 4 <- profiled slot
    k_gemm<F_IN, 32, true><<<NB32, 256>>>(x, W0, Wres0,          // 5
                                          asrc0, adst0, b0);

    k_agg<<<NB8, 256>>>(0, 1);                                   // 6

    // layers 1..3 (F=64), activation after layers 1,2 only
    for (int i = 0; i < 3; i++) {
        k_gemm<C, C, false><<<NB32, 256>>>(nullptr,
                                           W + (size_t)i * C * C,
                                           Wres + (size_t)i * C * C,
                                           asrc + (size_t)i * C,
                                           adst + (size_t)i * C,
                                           b + (size_t)i * C);
        k_agg<<<NB8, 256>>>(i + 1, (i < 2) ? 1 : 0);
    }

    k_out<<<G_GR, D_OUT>>>(batch, Wout, bout, out);
}

// round 13
// speedup vs baseline: 1.1924x; 1.0129x over previous
#include <cuda_runtime.h>
#include <cuda_fp16.h>
#include <math.h>
#include <math_constants.h>

#define N_NODES 50000
#define N_EDGES 1000000
#define F_IN    30
#define C       64
#define EDIM    11
#define G_GR    1024
#define D_OUT   256
#define NLAYERS 4
#define SCAN_BLKS ((N_NODES + 255) / 256)   // 196
#define NB32_G   ((N_NODES + 31) / 32)      // 1563 gemm blocks

// ---------------- device scratch (static, allocation-free) ----------------
__device__ float    g_feat[N_NODES * C];       // layer input / aggregated output (fp32)
__device__ __half2  g_hwh[N_NODES * (C / 2)];  // h = x @ W, fp16, ch (2l,2l+1) at [row*32+l]
__device__ float    g_res[N_NODES * C];        // x @ Wres + b
__device__ float    g_hs[N_NODES];
__device__ float    g_hd[N_NODES];
__device__ int      g_rowptr[N_NODES];         // block-LOCAL exclusive scan (add g_boff)
__device__ int      g_deg[N_NODES];            // per-node degree (written by scanA)
__device__ int      g_cnt[N_NODES];            // zero-init; returns to 0 every launch
__device__ int4     g_edge4[N_EDGES];          // CSR: {src, h2(et0,et1), src, h2(et2,et3)}
__device__ float    g_aeff[NLAYERS * EDIM];    // We @ ae per layer
__device__ int      g_boff[SCAN_BLKS];         // per-block segment base (atomic-assigned)
__device__ int      g_total;                   // atomic cursor (zeroed by k_pre)

// ---------------- packed f32x2 helpers (Blackwell FFMA2 pipe) -------------
__device__ __forceinline__ unsigned long long pack2(float x, float y) {
    unsigned long long r;
    asm("mov.b64 %0, {%1, %2};" : "=l"(r)
        : "r"(__float_as_uint(x)), "r"(__float_as_uint(y)));
    return r;
}
__device__ __forceinline__ void unpack2(unsigned long long v, float& x, float& y) {
    unsigned lo, hi;
    asm("mov.b64 {%0, %1}, %2;" : "=r"(lo), "=r"(hi) : "l"(v));
    x = __uint_as_float(lo); y = __uint_as_float(hi);
}
__device__ __forceinline__ unsigned long long fma2(unsigned long long a,
                                                   unsigned long long b,
                                                   unsigned long long c) {
    unsigned long long d;
    asm("fma.rn.f32x2 %0, %1, %2, %3;" : "=l"(d) : "l"(a), "l"(b), "l"(c));
    return d;
}

// ---------------- shared GEMM body (used by k_pre and k_gemm) -------------
template <int F, int FS, bool FIRST>
__device__ __forceinline__ void gemm_body(
    const float* __restrict__ xin, const float* __restrict__ W,
    const float* __restrict__ Wres, const float* __restrict__ asrcv,
    const float* __restrict__ adstv, const float* __restrict__ bv, int bid) {
    constexpr int KT = 32;
    __shared__ float Wc[KT * 2 * C];   // 16KB staged (W,Wres) interleaved
    __shared__ float xs[8][4][FS];
    __shared__ float as_[C], ad_[C], bs_[C];
    int tid = threadIdx.x;
    if (tid < C) { as_[tid] = asrcv[tid]; ad_[tid] = adstv[tid]; bs_[tid] = bv[tid]; }
    int lane = tid & 31, wid = tid >> 5;
    int c0 = 2 * lane;
    int row0 = bid * 32 + wid * 4;
    #pragma unroll
    for (int r = 0; r < 4; r++) {
        int row = row0 + r;
        if (row < N_NODES) {
            const float* xr = FIRST ? (xin + (size_t)row * F) : (g_feat + (size_t)row * F);
            if (lane < F) xs[wid][r][lane] = xr[lane];
            if (F > 32 && lane + 32 < F) xs[wid][r][lane + 32] = xr[lane + 32];
        }
    }
    unsigned long long A0[4] = {0, 0, 0, 0};   // packed (h, res) for channel c0
    unsigned long long A1[4] = {0, 0, 0, 0};   // packed (h, res) for channel c0+1
    #pragma unroll
    for (int kt = 0; kt < F; kt += KT) {
        const int len = (F - kt < KT) ? (F - kt) : KT;
        __syncthreads();   // first iter: covers xs; later: Wc readers done
        for (int i = tid; i < len * C; i += 256) {
            int k = i / C, c = i % C;
            Wc[k * 2 * C + 2 * c]     = W[(size_t)(kt + k) * C + c];
            Wc[k * 2 * C + 2 * c + 1] = Wres[(size_t)(kt + k) * C + c];
        }
        __syncthreads();
        for (int k = 0; k < len; k++) {
            ulonglong2 wp = *(const ulonglong2*)&Wc[k * 2 * C + 4 * lane];
            #pragma unroll
            for (int r = 0; r < 4; r++) {
                float xv = xs[wid][r][kt + k];
                unsigned long long xp = pack2(xv, xv);
                A0[r] = fma2(xp, wp.x, A0[r]);
                A1[r] = fma2(xp, wp.y, A1[r]);
            }
        }
    }
    float2 asv = *(const float2*)&as_[c0];
    float2 adv = *(const float2*)&ad_[c0];
    float2 bsv = *(const float2*)&bs_[c0];
    #pragma unroll
    for (int r = 0; r < 4; r++) {
        int row = row0 + r;
        if (row >= N_NODES) break;
        float h0, r0, h1, r1;
        unpack2(A0[r], h0, r0);
        unpack2(A1[r], h1, r1);
        g_hwh[(size_t)row * 32 + lane] = __floats2half2_rn(h0, h1);
        float2 rv; rv.x = r0 + bsv.x; rv.y = r1 + bsv.y;
        *(float2*)&g_res[(size_t)row * C + c0] = rv;
        float p = h0 * asv.x + h1 * asv.y;
        float q = h0 * adv.x + h1 * adv.y;
        #pragma unroll
        for (int off = 16; off; off >>= 1) {
            p += __shfl_xor_sync(0xffffffffu, p, off);
            q += __shfl_xor_sync(0xffffffffu, q, off);
        }
        if (lane == 0) { g_hs[row] = p; g_hd[row] = q; }
    }
}

// ---------------- pre: hist + aeff + g_total reset + gemm0 (merged) -------
__global__ void __launch_bounds__(256, 5)
k_pre(const int* __restrict__ edge_index,
      const float* __restrict__ x,
      const float* __restrict__ W0,  const float* __restrict__ Wres0,
      const float* __restrict__ asrc0, const float* __restrict__ adst0,
      const float* __restrict__ b0,
      const float* __restrict__ We0, const float* __restrict__ ae0,
      const float* __restrict__ We,  const float* __restrict__ ae) {
    int tid = threadIdx.x;
    int bid = blockIdx.x;
    if (bid == 0) {
        if (tid == 0) g_total = 0;
        if (tid < NLAYERS * EDIM) {
            int l = tid / EDIM, d = tid % EDIM;
            const float* we = (l == 0) ? We0 : (We + (size_t)(l - 1) * EDIM * C);
            const float* av = (l == 0) ? ae0 : (ae + (size_t)(l - 1) * C);
            float s = 0.0f;
            #pragma unroll
            for (int c = 0; c < C; c++) s = fmaf(we[d * C + c], av[c], s);
            g_aeff[tid] = s;
        }
    }
    int e = bid * 256 + tid;
    if (e < N_EDGES) atomicAdd(&g_cnt[edge_index[N_EDGES + e]], 1);
    if (bid < NB32_G)
        gemm_body<F_IN, 32, true>(x, W0, Wres0, asrc0, adst0, b0, bid);
}

// scanA: block-local exclusive scan; block segment base via atomic cursor.
// Segment placement is order-free (any disjoint partition is a valid CSR).
__global__ void k_scanA() {
    __shared__ int wsum[8];
    int tid = threadIdx.x, lane = tid & 31, wid = tid >> 5;
    int i = blockIdx.x * 256 + tid;
    int c = (i < N_NODES) ? g_cnt[i] : 0;
    int inc = c;
    #pragma unroll
    for (int o = 1; o < 32; o <<= 1) {
        int t = __shfl_up_sync(0xffffffffu, inc, o);
        if (lane >= o) inc += t;
    }
    if (lane == 31) wsum[wid] = inc;
    __syncthreads();
    if (tid < 8) {
        int v = wsum[tid];
        #pragma unroll
        for (int o = 1; o < 8; o <<= 1) {
            int t = __shfl_up_sync(0x000000ffu, v, o);
            if ((tid & 7) >= o) v += t;
        }
        wsum[tid] = v;
    }
    __syncthreads();
    int excl = (inc - c) + ((wid > 0) ? wsum[wid - 1] : 0);
    if (i < N_NODES) { g_rowptr[i] = excl; g_deg[i] = c; }   // cnt NOT zeroed
    if (tid == 255) g_boff[blockIdx.x] = atomicAdd(&g_total, wsum[7]);
}

// ---------------- fused scatter + edge-term: ONE int4 store per edge ------
__global__ void k_scatter_et(const int* __restrict__ edge_index,
                             const float* __restrict__ edge_attr) {
    __shared__ float sa[NLAYERS * EDIM];
    __shared__ float sea[256 * EDIM];
    int tid = threadIdx.x;
    if (tid < NLAYERS * EDIM) sa[tid] = g_aeff[tid];
    int base = blockIdx.x * 256;
    int nE = N_EDGES - base; if (nE > 256) nE = 256;
    for (int i = tid; i < nE * EDIM; i += 256)
        sea[i] = edge_attr[(size_t)base * EDIM + i];
    __syncthreads();
    int e = base + tid;
    if (e >= N_EDGES) return;
    int s = edge_index[e];
    int d = edge_index[N_EDGES + e];
    int old = atomicSub(&g_cnt[d], 1);             // old in [1..deg]; drains cnt to 0
    int pos = g_rowptr[d] + g_boff[d >> 8] + old - 1;
    float ea[EDIM];
    #pragma unroll
    for (int j = 0; j < EDIM; j++) ea[j] = sea[tid * EDIM + j];
    float et[NLAYERS];
    #pragma unroll
    for (int l = 0; l < NLAYERS; l++) {
        float t = 0.0f;
        #pragma unroll
        for (int j = 0; j < EDIM; j++) t = fmaf(ea[j], sa[l * EDIM + j], t);
        et[l] = t;
    }
    __half2 h01 = __floats2half2_rn(et[0], et[1]);
    __half2 h23 = __floats2half2_rn(et[2], et[3]);
    g_edge4[pos] = make_int4(s, (int)*(unsigned*)&h01, s, (int)*(unsigned*)&h23);
}

// ---------------- node GEMM (layers 1..3) ----------------
template <int F, int FS, bool FIRST>
__global__ void __launch_bounds__(256, 5)
k_gemm(const float* __restrict__ xin, const float* __restrict__ W,
       const float* __restrict__ Wres, const float* __restrict__ asrcv,
       const float* __restrict__ adstv, const float* __restrict__ bv) {
    gemm_body<F, FS, FIRST>(xin, W, Wres, asrcv, adstv, bv, blockIdx.x);
}

// ---------------- per-dst softmax aggregation (no max-shift) --------------
__global__ void k_agg(int layer, int act) {
    int d = blockIdx.x * 8 + (threadIdx.x >> 5);
    if (d >= N_NODES) return;
    int lane = threadIdx.x & 31;
    int beg = g_rowptr[d] + g_boff[d >> 8];
    int end = beg + g_deg[d];
    float hdv = g_hd[d];
    const int2* __restrict__ ed2 = (const int2*)g_edge4;
    const int half_sel = layer >> 1;        // which int2 of the int4
    const bool hi_sel  = (layer & 1) != 0;  // which half of the half2
    float s = 0.0f, acc0 = 0.0f, acc1 = 0.0f;

    for (int base = beg; base < end; base += 32) {
        int p = base + lane;
        bool valid = (p < end);
        int src = 0;
        float pe = 0.0f;
        if (valid) {
            int2 v = ed2[2 * (size_t)p + half_sel];
            src = v.x;
            __half2 hh = *(__half2*)&v.y;
            float etv = hi_sel ? __high2float(hh) : __low2float(hh);
            float alpha = g_hs[src] + hdv + etv;
            alpha = (alpha > 0.0f) ? alpha : 0.2f * alpha;   // leaky_relu 0.2
            pe = __expf(alpha);
        }
        s += pe;
        int nval = end - base; if (nval > 32) nval = 32;
        for (int j = 0; j < nval; j++) {
            float pj = __shfl_sync(0xffffffffu, pe, j);
            int   sj = __shfl_sync(0xffffffffu, src, j);
            float2 h = __half22float2(g_hwh[(size_t)sj * 32 + lane]);
            acc0 = fmaf(pj, h.x, acc0);
            acc1 = fmaf(pj, h.y, acc1);
        }
    }
    #pragma unroll
    for (int off = 16; off; off >>= 1)
        s += __shfl_xor_sync(0xffffffffu, s, off);

    float w = 1.0f / (s + 1e-16f);
    size_t o = (size_t)d * C + 2 * lane;
    float2 rv = *(const float2*)&g_res[o];
    float o0 = acc0 * w + rv.x;
    float o1 = acc1 * w + rv.y;
    if (act) {
        o0 = (o0 > 0.0f) ? o0 : 0.01f * o0;
        o1 = (o1 > 0.0f) ? o1 : 0.01f * o1;
    }
    float2 ov; ov.x = o0; ov.y = o1;
    *(float2*)&g_feat[o] = ov;
}

// ---------------- fused pooling + final projection ----------------
__global__ void k_out(const int* __restrict__ batch,
                      const float* __restrict__ Wout, const float* __restrict__ bout,
                      float* __restrict__ out) {
    int g = blockIdx.x;
    int t = threadIdx.x;  // 256 threads
    __shared__ int range[2];
    __shared__ float smx[4][C], ssm[4][C];
    __shared__ float pooled[2 * C];
    if (t == 0) {
        int lo = 0, hi = N_NODES;
        while (lo < hi) { int mid = (lo + hi) >> 1; if (batch[mid] < g) lo = mid + 1; else hi = mid; }
        range[0] = lo;
        lo = range[0]; hi = N_NODES;
        while (lo < hi) { int mid = (lo + hi) >> 1; if (batch[mid] < g + 1) lo = mid + 1; else hi = mid; }
        range[1] = lo;
    }
    __syncthreads();
    int start = range[0], endn = range[1];
    int c = t & 63, q = t >> 6;
    float mx = -CUDART_INF_F, sm = 0.0f;
    for (int n = start + q; n < endn; n += 4) {
        float v = g_feat[(size_t)n * C + c];
        mx = fmaxf(mx, v);
        sm += v;
    }
    smx[q][c] = mx; ssm[q][c] = sm;
    __syncthreads();
    if (t < C) {
        float M = fmaxf(fmaxf(smx[0][t], smx[1][t]), fmaxf(smx[2][t], smx[3][t]));
        float S = ssm[0][t] + ssm[1][t] + ssm[2][t] + ssm[3][t];
        if (!isfinite(M)) M = 0.0f;   // empty graph
        float cnt = (float)(endn - start); if (cnt < 1.0f) cnt = 1.0f;
        float mn = S / cnt;
        pooled[t]     = (M > 0.0f) ? M : 0.01f * M;
        pooled[C + t] = (mn > 0.0f) ? mn : 0.01f * mn;
    }
    __syncthreads();
    float acc = bout[t];
    #pragma unroll
    for (int k = 0; k < 2 * C; k++)
        acc = fmaf(pooled[k], Wout[(size_t)k * D_OUT + t], acc);
    out[(size_t)g * D_OUT + t] = acc;
}

// ---------------- launch (agg0 in profiled slot 4) ------------------------
extern "C" void kernel_launch(void* const* d_in, const int* in_sizes, int n_in,
                              void* d_out, int out_size) {
    const float* x      = (const float*)d_in[0];
    const float* eattr  = (const float*)d_in[1];
    const float* W0     = (const float*)d_in[2];
    const float* asrc0  = (const float*)d_in[3];
    const float* adst0  = (const float*)d_in[4];
    const float* We0    = (const float*)d_in[5];
    const float* ae0    = (const float*)d_in[6];
    const float* Wres0  = (const float*)d_in[7];
    const float* b0     = (const float*)d_in[8];
    const float* W      = (const float*)d_in[9];
    const float* asrc   = (const float*)d_in[10];
    const float* adst   = (const float*)d_in[11];
    const float* We     = (const float*)d_in[12];
    const float* ae     = (const float*)d_in[13];
    const float* Wres   = (const float*)d_in[14];
    const float* b      = (const float*)d_in[15];
    const float* Wout   = (const float*)d_in[16];
    const float* bout   = (const float*)d_in[17];
    const int*   eidx   = (const int*)d_in[18];
    const int*   batch  = (const int*)d_in[19];
    float* out = (float*)d_out;

    const int EB   = (N_EDGES + 255) / 256;
    const int NB8  = (N_NODES + 7) / 8;
    const int NB32 = (N_NODES + 31) / 32;

    k_pre<<<EB, 256>>>(eidx, x, W0, Wres0, asrc0, adst0, b0,     // 1 (hist+aeff+gemm0)
                       We0, ae0, We, ae);
    k_scanA<<<SCAN_BLKS, 256>>>();                               // 2
    k_scatter_et<<<EB, 256>>>(eidx, eattr);                      // 3
    k_agg<<<NB8, 256>>>(0, 1);                                   // 4 <- profiled slot

    // layers 1..3 (F=64), activation after layers 1,2 only
    for (int i = 0; i < 3; i++) {
        k_gemm<C, C, false><<<NB32, 256>>>(nullptr,
                                           W + (size_t)i * C * C,
                                           Wres + (size_t)i * C * C,
                                           asrc + (size_t)i * C,
                                           adst + (size_t)i * C,
                                           b + (size_t)i * C);
        k_agg<<<NB8, 256>>>(i + 1, (i < 2) ? 1 : 0);
    }

    k_out<<<G_GR, D_OUT>>>(batch, Wout, bout, out);
}

// round 14
// speedup vs baseline: 1.2075x; 1.0127x over previous
#include <cuda_runtime.h>
#include <cuda_fp16.h>
#include <math.h>
#include <math_constants.h>

#define N_NODES 50000
#define N_EDGES 1000000
#define F_IN    30
#define C       64
#define EDIM    11
#define G_GR    1024
#define D_OUT   256
#define NLAYERS 4
#define SCAN_BLKS ((N_NODES + 255) / 256)   // 196
#define NB32_G   ((N_NODES + 31) / 32)      // 1563 gemm blocks

// ---------------- device scratch (static, allocation-free) ----------------
__device__ float    g_feat[N_NODES * C];       // layer input / aggregated output (fp32)
__device__ __half2  g_hwh[N_NODES * (C / 2)];  // h = x @ W, fp16, ch (2l,2l+1) at [row*32+l]
__device__ float    g_res[N_NODES * C];        // x @ Wres + b
__device__ float    g_hs[N_NODES];
__device__ float    g_hd[N_NODES];
__device__ int      g_rowptr[N_NODES];         // block-LOCAL exclusive scan (add g_boff)
__device__ int      g_deg[N_NODES];            // per-node degree (written by scanA)
__device__ int      g_cnt[N_NODES];            // zero-init; returns to 0 every launch
__device__ int4     g_edge4[N_EDGES];          // CSR: {src, h2(et0,et1), src, h2(et2,et3)}
__device__ float    g_aeff[NLAYERS * EDIM];    // We @ ae per layer
__device__ int      g_boff[SCAN_BLKS];         // per-block segment base (atomic-assigned)
__device__ int      g_total;                   // atomic cursor (zeroed by k_pre)

// ---------------- packed f32x2 helpers (Blackwell FFMA2 pipe) -------------
__device__ __forceinline__ unsigned long long pack2(float x, float y) {
    unsigned long long r;
    asm("mov.b64 %0, {%1, %2};" : "=l"(r)
        : "r"(__float_as_uint(x)), "r"(__float_as_uint(y)));
    return r;
}
__device__ __forceinline__ void unpack2(unsigned long long v, float& x, float& y) {
    unsigned lo, hi;
    asm("mov.b64 {%0, %1}, %2;" : "=r"(lo), "=r"(hi) : "l"(v));
    x = __uint_as_float(lo); y = __uint_as_float(hi);
}
__device__ __forceinline__ unsigned long long fma2(unsigned long long a,
                                                   unsigned long long b,
                                                   unsigned long long c) {
    unsigned long long d;
    asm("fma.rn.f32x2 %0, %1, %2, %3;" : "=l"(d) : "l"(a), "l"(b), "l"(c));
    return d;
}

// ---------------- shared GEMM body (used by k_pre and k_gemm) -------------
template <int F, int FS, bool FIRST>
__device__ __forceinline__ void gemm_body(
    const float* __restrict__ xin, const float* __restrict__ W,
    const float* __restrict__ Wres, const float* __restrict__ asrcv,
    const float* __restrict__ adstv, const float* __restrict__ bv, int bid) {
    constexpr int KT = 32;
    __shared__ float Wc[KT * 2 * C];   // 16KB staged (W,Wres) interleaved
    __shared__ float xs[8][4][FS];
    __shared__ float as_[C], ad_[C], bs_[C];
    int tid = threadIdx.x;
    if (tid < C) { as_[tid] = asrcv[tid]; ad_[tid] = adstv[tid]; bs_[tid] = bv[tid]; }
    int lane = tid & 31, wid = tid >> 5;
    int c0 = 2 * lane;
    int row0 = bid * 32 + wid * 4;
    #pragma unroll
    for (int r = 0; r < 4; r++) {
        int row = row0 + r;
        if (row < N_NODES) {
            const float* xr = FIRST ? (xin + (size_t)row * F) : (g_feat + (size_t)row * F);
            if (lane < F) xs[wid][r][lane] = xr[lane];
            if (F > 32 && lane + 32 < F) xs[wid][r][lane + 32] = xr[lane + 32];
        }
    }
    unsigned long long A0[4] = {0, 0, 0, 0};   // packed (h, res) for channel c0
    unsigned long long A1[4] = {0, 0, 0, 0};   // packed (h, res) for channel c0+1
    #pragma unroll
    for (int kt = 0; kt < F; kt += KT) {
        const int len = (F - kt < KT) ? (F - kt) : KT;
        __syncthreads();   // first iter: covers xs; later: Wc readers done
        for (int i = tid; i < len * C; i += 256) {
            int k = i / C, c = i % C;
            Wc[k * 2 * C + 2 * c]     = W[(size_t)(kt + k) * C + c];
            Wc[k * 2 * C + 2 * c + 1] = Wres[(size_t)(kt + k) * C + c];
        }
        __syncthreads();
        for (int k = 0; k < len; k++) {
            ulonglong2 wp = *(const ulonglong2*)&Wc[k * 2 * C + 4 * lane];
            #pragma unroll
            for (int r = 0; r < 4; r++) {
                float xv = xs[wid][r][kt + k];
                unsigned long long xp = pack2(xv, xv);
                A0[r] = fma2(xp, wp.x, A0[r]);
                A1[r] = fma2(xp, wp.y, A1[r]);
            }
        }
    }
    float2 asv = *(const float2*)&as_[c0];
    float2 adv = *(const float2*)&ad_[c0];
    float2 bsv = *(const float2*)&bs_[c0];
    #pragma unroll
    for (int r = 0; r < 4; r++) {
        int row = row0 + r;
        if (row >= N_NODES) break;
        float h0, r0, h1, r1;
        unpack2(A0[r], h0, r0);
        unpack2(A1[r], h1, r1);
        g_hwh[(size_t)row * 32 + lane] = __floats2half2_rn(h0, h1);
        float2 rv; rv.x = r0 + bsv.x; rv.y = r1 + bsv.y;
        *(float2*)&g_res[(size_t)row * C + c0] = rv;
        float p = h0 * asv.x + h1 * asv.y;
        float q = h0 * adv.x + h1 * adv.y;
        #pragma unroll
        for (int off = 16; off; off >>= 1) {
            p += __shfl_xor_sync(0xffffffffu, p, off);
            q += __shfl_xor_sync(0xffffffffu, q, off);
        }
        if (lane == 0) { g_hs[row] = p; g_hd[row] = q; }
    }
}

// ---------------- pre: hist + aeff + g_total reset + gemm0 (merged) -------
__global__ void __launch_bounds__(256, 5)
k_pre(const int* __restrict__ edge_index,
      const float* __restrict__ x,
      const float* __restrict__ W0,  const float* __restrict__ Wres0,
      const float* __restrict__ asrc0, const float* __restrict__ adst0,
      const float* __restrict__ b0,
      const float* __restrict__ We0, const float* __restrict__ ae0,
      const float* __restrict__ We,  const float* __restrict__ ae) {
    int tid = threadIdx.x;
    int bid = blockIdx.x;
    if (bid == 0) {
        if (tid == 0) g_total = 0;
        if (tid < NLAYERS * EDIM) {
            int l = tid / EDIM, d = tid % EDIM;
            const float* we = (l == 0) ? We0 : (We + (size_t)(l - 1) * EDIM * C);
            const float* av = (l == 0) ? ae0 : (ae + (size_t)(l - 1) * C);
            float s = 0.0f;
            #pragma unroll
            for (int c = 0; c < C; c++) s = fmaf(we[d * C + c], av[c], s);
            g_aeff[tid] = s;
        }
    }
    int e = bid * 256 + tid;
    if (e < N_EDGES) atomicAdd(&g_cnt[edge_index[N_EDGES + e]], 1);
    if (bid < NB32_G)
        gemm_body<F_IN, 32, true>(x, W0, Wres0, asrc0, adst0, b0, bid);
}

// scanA: block-local exclusive scan; block segment base via atomic cursor.
__global__ void k_scanA() {
    __shared__ int wsum[8];
    int tid = threadIdx.x, lane = tid & 31, wid = tid >> 5;
    int i = blockIdx.x * 256 + tid;
    int c = (i < N_NODES) ? g_cnt[i] : 0;
    int inc = c;
    #pragma unroll
    for (int o = 1; o < 32; o <<= 1) {
        int t = __shfl_up_sync(0xffffffffu, inc, o);
        if (lane >= o) inc += t;
    }
    if (lane == 31) wsum[wid] = inc;
    __syncthreads();
    if (tid < 8) {
        int v = wsum[tid];
        #pragma unroll
        for (int o = 1; o < 8; o <<= 1) {
            int t = __shfl_up_sync(0x000000ffu, v, o);
            if ((tid & 7) >= o) v += t;
        }
        wsum[tid] = v;
    }
    __syncthreads();
    int excl = (inc - c) + ((wid > 0) ? wsum[wid - 1] : 0);
    if (i < N_NODES) { g_rowptr[i] = excl; g_deg[i] = c; }   // cnt NOT zeroed
    if (tid == 255) g_boff[blockIdx.x] = atomicAdd(&g_total, wsum[7]);
}

// ---------------- fused scatter + edge-term: ONE int4 store per edge ------
__global__ void k_scatter_et(const int* __restrict__ edge_index,
                             const float* __restrict__ edge_attr) {
    __shared__ float sa[NLAYERS * EDIM];
    __shared__ float sea[256 * EDIM];
    int tid = threadIdx.x;
    if (tid < NLAYERS * EDIM) sa[tid] = g_aeff[tid];
    int base = blockIdx.x * 256;
    int nE = N_EDGES - base; if (nE > 256) nE = 256;
    for (int i = tid; i < nE * EDIM; i += 256)
        sea[i] = edge_attr[(size_t)base * EDIM + i];
    __syncthreads();
    int e = base + tid;
    if (e >= N_EDGES) return;
    int s = edge_index[e];
    int d = edge_index[N_EDGES + e];
    int old = atomicSub(&g_cnt[d], 1);             // old in [1..deg]; drains cnt to 0
    int pos = g_rowptr[d] + g_boff[d >> 8] + old - 1;
    float ea[EDIM];
    #pragma unroll
    for (int j = 0; j < EDIM; j++) ea[j] = sea[tid * EDIM + j];
    float et[NLAYERS];
    #pragma unroll
    for (int l = 0; l < NLAYERS; l++) {
        float t = 0.0f;
        #pragma unroll
        for (int j = 0; j < EDIM; j++) t = fmaf(ea[j], sa[l * EDIM + j], t);
        et[l] = t;
    }
    __half2 h01 = __floats2half2_rn(et[0], et[1]);
    __half2 h23 = __floats2half2_rn(et[2], et[3]);
    g_edge4[pos] = make_int4(s, (int)*(unsigned*)&h01, s, (int)*(unsigned*)&h23);
}

// ---------------- node GEMM (layers 1..3) ----------------
template <int F, int FS, bool FIRST>
__global__ void __launch_bounds__(256, 5)
k_gemm(const float* __restrict__ xin, const float* __restrict__ W,
       const float* __restrict__ Wres, const float* __restrict__ asrcv,
       const float* __restrict__ adstv, const float* __restrict__ bv) {
    gemm_body<F, FS, FIRST>(xin, W, Wres, asrcv, adstv, bv, blockIdx.x);
}

// ---------------- per-dst softmax aggregation ----------------
// Fixed 32-iteration zero-padded inner loop: invalid lanes hold pe=0, so
// shfl(pe,j) for j>=nval is exactly 0 and fma(0,h,acc)==acc. Removes the
// dynamic trip count -> compiler unrolls, batches LDGs (MLP), no branches.
__global__ void k_agg(int layer, int act) {
    int d = blockIdx.x * 8 + (threadIdx.x >> 5);
    if (d >= N_NODES) return;
    int lane = threadIdx.x & 31;
    int beg = g_rowptr[d] + g_boff[d >> 8];
    int end = beg + g_deg[d];
    float hdv = g_hd[d];
    const int2* __restrict__ ed2 = (const int2*)g_edge4;
    const int half_sel = layer >> 1;        // which int2 of the int4
    const bool hi_sel  = (layer & 1) != 0;  // which half of the half2
    float s = 0.0f, acc0 = 0.0f, acc1 = 0.0f;

    for (int base = beg; base < end; base += 32) {
        int p = base + lane;
        bool valid = (p < end);
        int src = 0;
        float pe = 0.0f;
        if (valid) {
            int2 v = ed2[2 * (size_t)p + half_sel];
            src = v.x;
            __half2 hh = *(__half2*)&v.y;
            float etv = hi_sel ? __high2float(hh) : __low2float(hh);
            float alpha = g_hs[src] + hdv + etv;
            alpha = (alpha > 0.0f) ? alpha : 0.2f * alpha;   // leaky_relu 0.2
            pe = __expf(alpha);
        }
        s += pe;
        #pragma unroll 4
        for (int j = 0; j < 32; j++) {
            float pj = __shfl_sync(0xffffffffu, pe, j);   // 0 beyond nval
            int   sj = __shfl_sync(0xffffffffu, src, j);
            float2 h = __half22float2(g_hwh[(size_t)sj * 32 + lane]);
            acc0 = fmaf(pj, h.x, acc0);
            acc1 = fmaf(pj, h.y, acc1);
        }
    }
    #pragma unroll
    for (int off = 16; off; off >>= 1)
        s += __shfl_xor_sync(0xffffffffu, s, off);

    float w = 1.0f / (s + 1e-16f);
    size_t o = (size_t)d * C + 2 * lane;
    float2 rv = *(const float2*)&g_res[o];
    float o0 = acc0 * w + rv.x;
    float o1 = acc1 * w + rv.y;
    if (act) {
        o0 = (o0 > 0.0f) ? o0 : 0.01f * o0;
        o1 = (o1 > 0.0f) ? o1 : 0.01f * o1;
    }
    float2 ov; ov.x = o0; ov.y = o1;
    *(float2*)&g_feat[o] = ov;
}

// ---------------- fused pooling + final projection ----------------
__global__ void k_out(const int* __restrict__ batch,
                      const float* __restrict__ Wout, const float* __restrict__ bout,
                      float* __restrict__ out) {
    int g = blockIdx.x;
    int t = threadIdx.x;  // 256 threads
    __shared__ int range[2];
    __shared__ float smx[4][C], ssm[4][C];
    __shared__ float pooled[2 * C];
    if (t == 0) {
        int lo = 0, hi = N_NODES;
        while (lo < hi) { int mid = (lo + hi) >> 1; if (batch[mid] < g) lo = mid + 1; else hi = mid; }
        range[0] = lo;
        lo = range[0]; hi = N_NODES;
        while (lo < hi) { int mid = (lo + hi) >> 1; if (batch[mid] < g + 1) lo = mid + 1; else hi = mid; }
        range[1] = lo;
    }
    __syncthreads();
    int start = range[0], endn = range[1];
    int c = t & 63, q = t >> 6;
    float mx = -CUDART_INF_F, sm = 0.0f;
    for (int n = start + q; n < endn; n += 4) {
        float v = g_feat[(size_t)n * C + c];
        mx = fmaxf(mx, v);
        sm += v;
    }
    smx[q][c] = mx; ssm[q][c] = sm;
    __syncthreads();
    if (t < C) {
        float M = fmaxf(fmaxf(smx[0][t], smx[1][t]), fmaxf(smx[2][t], smx[3][t]));
        float S = ssm[0][t] + ssm[1][t] + ssm[2][t] + ssm[3][t];
        if (!isfinite(M)) M = 0.0f;   // empty graph
        float cnt = (float)(endn - start); if (cnt < 1.0f) cnt = 1.0f;
        float mn = S / cnt;
        pooled[t]     = (M > 0.0f) ? M : 0.01f * M;
        pooled[C + t] = (mn > 0.0f) ? mn : 0.01f * mn;
    }
    __syncthreads();
    float acc = bout[t];
    #pragma unroll
    for (int k = 0; k < 2 * C; k++)
        acc = fmaf(pooled[k], Wout[(size_t)k * D_OUT + t], acc);
    out[(size_t)g * D_OUT + t] = acc;
}

// ---------------- launch (agg0 in profiled slot 4) ------------------------
extern "C" void kernel_launch(void* const* d_in, const int* in_sizes, int n_in,
                              void* d_out, int out_size) {
    const float* x      = (const float*)d_in[0];
    const float* eattr  = (const float*)d_in[1];
    const float* W0     = (const float*)d_in[2];
    const float* asrc0  = (const float*)d_in[3];
    const float* adst0  = (const float*)d_in[4];
    const float* We0    = (const float*)d_in[5];
    const float* ae0    = (const float*)d_in[6];
    const float* Wres0  = (const float*)d_in[7];
    const float* b0     = (const float*)d_in[8];
    const float* W      = (const float*)d_in[9];
    const float* asrc   = (const float*)d_in[10];
    const float* adst   = (const float*)d_in[11];
    const float* We     = (const float*)d_in[12];
    const float* ae     = (const float*)d_in[13];
    const float* Wres   = (const float*)d_in[14];
    const float* b      = (const float*)d_in[15];
    const float* Wout   = (const float*)d_in[16];
    const float* bout   = (const float*)d_in[17];
    const int*   eidx   = (const int*)d_in[18];
    const int*   batch  = (const int*)d_in[19];
    float* out = (float*)d_out;

    const int EB   = (N_EDGES + 255) / 256;
    const int NB8  = (N_NODES + 7) / 8;
    const int NB32 = (N_NODES + 31) / 32;

    k_pre<<<EB, 256>>>(eidx, x, W0, Wres0, asrc0, adst0, b0,     // 1 (hist+aeff+gemm0)
                       We0, ae0, We, ae);
    k_scanA<<<SCAN_BLKS, 256>>>();                               // 2
    k_scatter_et<<<EB, 256>>>(eidx, eattr);                      // 3
    k_agg<<<NB8, 256>>>(0, 1);                                   // 4 <- profiled slot

    // layers 1..3 (F=64), activation after layers 1,2 only
    for (int i = 0; i < 3; i++) {
        k_gemm<C, C, false><<<NB32, 256>>>(nullptr,
                                           W + (size_t)i * C * C,
                                           Wres + (size_t)i * C * C,
                                           asrc + (size_t)i * C,
                                           adst + (size_t)i * C,
                                           b + (size_t)i * C);
        k_agg<<<NB8, 256>>>(i + 1, (i < 2) ? 1 : 0);
    }

    k_out<<<G_GR, D_OUT>>>(batch, Wout, bout, out);
}

// round 15
// speedup vs baseline: 1.2942x; 1.0717x over previous
#include <cuda_runtime.h>
#include <cuda_fp16.h>
#include <math.h>
#include <math_constants.h>

#define N_NODES 50000
#define N_EDGES 1000000
#define F_IN    30
#define C       64
#define EDIM    11
#define G_GR    1024
#define D_OUT   256
#define NLAYERS 4
#define SCAN_BLKS ((N_NODES + 255) / 256)   // 196
#define NB32_G   ((N_NODES + 31) / 32)      // 1563 gemm blocks

// ---------------- device scratch (static, allocation-free) ----------------
__device__ float    g_feat[N_NODES * C];       // layer input / aggregated output (fp32)
__device__ __half2  g_hwh[N_NODES * (C / 2)];  // h = x @ W, fp16, ch (2l,2l+1) at [row*32+l]
__device__ float    g_res[N_NODES * C];        // x @ Wres + b
__device__ float    g_hs[N_NODES];
__device__ float    g_hd[N_NODES];
__device__ int      g_rowptr[N_NODES];         // block-LOCAL exclusive scan (add g_boff)
__device__ int      g_deg[N_NODES];            // per-node degree (written by scanA)
__device__ int      g_cnt[N_NODES];            // zero-init; returns to 0 every launch
__device__ int4     g_edge4[N_EDGES];          // CSR: {src, h2(et0,et1), src, h2(et2,et3)}
__device__ float    g_aeff[NLAYERS * EDIM];    // We @ ae per layer
__device__ int      g_boff[SCAN_BLKS];         // per-block segment base (atomic-assigned)
__device__ int      g_total;                   // atomic cursor (zeroed by k_pre)

// ---------------- packed f32x2 helpers (Blackwell FFMA2 pipe) -------------
__device__ __forceinline__ unsigned long long pack2(float x, float y) {
    unsigned long long r;
    asm("mov.b64 %0, {%1, %2};" : "=l"(r)
        : "r"(__float_as_uint(x)), "r"(__float_as_uint(y)));
    return r;
}
__device__ __forceinline__ void unpack2(unsigned long long v, float& x, float& y) {
    unsigned lo, hi;
    asm("mov.b64 {%0, %1}, %2;" : "=r"(lo), "=r"(hi) : "l"(v));
    x = __uint_as_float(lo); y = __uint_as_float(hi);
}
__device__ __forceinline__ unsigned long long fma2(unsigned long long a,
                                                   unsigned long long b,
                                                   unsigned long long c) {
    unsigned long long d;
    asm("fma.rn.f32x2 %0, %1, %2, %3;" : "=l"(d) : "l"(a), "l"(b), "l"(c));
    return d;
}

// ---------------- shared GEMM body (used by k_pre and k_gemm) -------------
template <int F, int FS, bool FIRST>
__device__ __forceinline__ void gemm_body(
    const float* __restrict__ xin, const float* __restrict__ W,
    const float* __restrict__ Wres, const float* __restrict__ asrcv,
    const float* __restrict__ adstv, const float* __restrict__ bv, int bid) {
    constexpr int KT = 32;
    __shared__ float Wc[KT * 2 * C];   // 16KB staged (W,Wres) interleaved
    __shared__ float xs[8][4][FS];
    __shared__ float as_[C], ad_[C], bs_[C];
    int tid = threadIdx.x;
    if (tid < C) { as_[tid] = asrcv[tid]; ad_[tid] = adstv[tid]; bs_[tid] = bv[tid]; }
    int lane = tid & 31, wid = tid >> 5;
    int c0 = 2 * lane;
    int row0 = bid * 32 + wid * 4;
    #pragma unroll
    for (int r = 0; r < 4; r++) {
        int row = row0 + r;
        if (row < N_NODES) {
            const float* xr = FIRST ? (xin + (size_t)row * F) : (g_feat + (size_t)row * F);
            if (lane < F) xs[wid][r][lane] = xr[lane];
            if (F > 32 && lane + 32 < F) xs[wid][r][lane + 32] = xr[lane + 32];
        }
    }
    unsigned long long A0[4] = {0, 0, 0, 0};   // packed (h, res) for channel c0
    unsigned long long A1[4] = {0, 0, 0, 0};   // packed (h, res) for channel c0+1
    #pragma unroll
    for (int kt = 0; kt < F; kt += KT) {
        const int len = (F - kt < KT) ? (F - kt) : KT;
        __syncthreads();   // first iter: covers xs; later: Wc readers done
        for (int i = tid; i < len * C; i += 256) {
            int k = i / C, c = i % C;
            Wc[k * 2 * C + 2 * c]     = W[(size_t)(kt + k) * C + c];
            Wc[k * 2 * C + 2 * c + 1] = Wres[(size_t)(kt + k) * C + c];
        }
        __syncthreads();
        for (int k = 0; k < len; k++) {
            ulonglong2 wp = *(const ulonglong2*)&Wc[k * 2 * C + 4 * lane];
            #pragma unroll
            for (int r = 0; r < 4; r++) {
                float xv = xs[wid][r][kt + k];
                unsigned long long xp = pack2(xv, xv);
                A0[r] = fma2(xp, wp.x, A0[r]);
                A1[r] = fma2(xp, wp.y, A1[r]);
            }
        }
    }
    float2 asv = *(const float2*)&as_[c0];
    float2 adv = *(const float2*)&ad_[c0];
    float2 bsv = *(const float2*)&bs_[c0];
    #pragma unroll
    for (int r = 0; r < 4; r++) {
        int row = row0 + r;
        if (row >= N_NODES) break;
        float h0, r0, h1, r1;
        unpack2(A0[r], h0, r0);
        unpack2(A1[r], h1, r1);
        g_hwh[(size_t)row * 32 + lane] = __floats2half2_rn(h0, h1);
        float2 rv; rv.x = r0 + bsv.x; rv.y = r1 + bsv.y;
        *(float2*)&g_res[(size_t)row * C + c0] = rv;
        float p = h0 * asv.x + h1 * asv.y;
        float q = h0 * adv.x + h1 * adv.y;
        #pragma unroll
        for (int off = 16; off; off >>= 1) {
            p += __shfl_xor_sync(0xffffffffu, p, off);
            q += __shfl_xor_sync(0xffffffffu, q, off);
        }
        if (lane == 0) { g_hs[row] = p; g_hd[row] = q; }
    }
}

// ---------------- pre: hist + aeff + g_total reset + gemm0 (merged) -------
__global__ void __launch_bounds__(256, 5)
k_pre(const int* __restrict__ edge_index,
      const float* __restrict__ x,
      const float* __restrict__ W0,  const float* __restrict__ Wres0,
      const float* __restrict__ asrc0, const float* __restrict__ adst0,
      const float* __restrict__ b0,
      const float* __restrict__ We0, const float* __restrict__ ae0,
      const float* __restrict__ We,  const float* __restrict__ ae) {
    int tid = threadIdx.x;
    int bid = blockIdx.x;
    if (bid == 0) {
        if (tid == 0) g_total = 0;
        if (tid < NLAYERS * EDIM) {
            int l = tid / EDIM, d = tid % EDIM;
            const float* we = (l == 0) ? We0 : (We + (size_t)(l - 1) * EDIM * C);
            const float* av = (l == 0) ? ae0 : (ae + (size_t)(l - 1) * C);
            float s = 0.0f;
            #pragma unroll
            for (int c = 0; c < C; c++) s = fmaf(we[d * C + c], av[c], s);
            g_aeff[tid] = s;
        }
    }
    int e = bid * 256 + tid;
    if (e < N_EDGES) atomicAdd(&g_cnt[edge_index[N_EDGES + e]], 1);
    if (bid < NB32_G)
        gemm_body<F_IN, 32, true>(x, W0, Wres0, asrc0, adst0, b0, bid);
}

// scanA: block-local exclusive scan; block segment base via atomic cursor.
__global__ void k_scanA() {
    __shared__ int wsum[8];
    int tid = threadIdx.x, lane = tid & 31, wid = tid >> 5;
    int i = blockIdx.x * 256 + tid;
    int c = (i < N_NODES) ? g_cnt[i] : 0;
    int inc = c;
    #pragma unroll
    for (int o = 1; o < 32; o <<= 1) {
        int t = __shfl_up_sync(0xffffffffu, inc, o);
        if (lane >= o) inc += t;
    }
    if (lane == 31) wsum[wid] = inc;
    __syncthreads();
    if (tid < 8) {
        int v = wsum[tid];
        #pragma unroll
        for (int o = 1; o < 8; o <<= 1) {
            int t = __shfl_up_sync(0x000000ffu, v, o);
            if ((tid & 7) >= o) v += t;
        }
        wsum[tid] = v;
    }
    __syncthreads();
    int excl = (inc - c) + ((wid > 0) ? wsum[wid - 1] : 0);
    if (i < N_NODES) { g_rowptr[i] = excl; g_deg[i] = c; }   // cnt NOT zeroed
    if (tid == 255) g_boff[blockIdx.x] = atomicAdd(&g_total, wsum[7]);
}

// ---------------- fused scatter + edge-term: ONE int4 store per edge ------
__global__ void __launch_bounds__(256, 6)
k_scatter_et(const int* __restrict__ edge_index,
             const float* __restrict__ edge_attr) {
    __shared__ float sa[NLAYERS * EDIM];
    __shared__ float sea[256 * EDIM];
    int tid = threadIdx.x;
    if (tid < NLAYERS * EDIM) sa[tid] = g_aeff[tid];
    int base = blockIdx.x * 256;
    int nE = N_EDGES - base; if (nE > 256) nE = 256;
    for (int i = tid; i < nE * EDIM; i += 256)
        sea[i] = edge_attr[(size_t)base * EDIM + i];
    __syncthreads();
    int e = base + tid;
    if (e >= N_EDGES) return;
    int s = edge_index[e];
    int d = edge_index[N_EDGES + e];
    int old = atomicSub(&g_cnt[d], 1);             // old in [1..deg]; drains cnt to 0
    int pos = g_rowptr[d] + g_boff[d >> 8] + old - 1;
    float ea[EDIM];
    #pragma unroll
    for (int j = 0; j < EDIM; j++) ea[j] = sea[tid * EDIM + j];
    float et[NLAYERS];
    #pragma unroll
    for (int l = 0; l < NLAYERS; l++) {
        float t = 0.0f;
        #pragma unroll
        for (int j = 0; j < EDIM; j++) t = fmaf(ea[j], sa[l * EDIM + j], t);
        et[l] = t;
    }
    __half2 h01 = __floats2half2_rn(et[0], et[1]);
    __half2 h23 = __floats2half2_rn(et[2], et[3]);
    g_edge4[pos] = make_int4(s, (int)*(unsigned*)&h01, s, (int)*(unsigned*)&h23);
}

// ---------------- node GEMM (layers 1..3) ----------------
template <int F, int FS, bool FIRST>
__global__ void __launch_bounds__(256, 5)
k_gemm(const float* __restrict__ xin, const float* __restrict__ W,
       const float* __restrict__ Wres, const float* __restrict__ asrcv,
       const float* __restrict__ adstv, const float* __restrict__ bv) {
    gemm_body<F, FS, FIRST>(xin, W, Wres, asrcv, adstv, bv, blockIdx.x);
}

// ---------------- per-dst softmax aggregation ----------------
// Inner gather runs in fully-unrolled 8-groups up to ceil(nval/8)*8:
// zero-padded (pe=0 beyond nval -> fma is a no-op), keeps 8-deep LDG
// batching, cuts padded slots ~37% -> ~12% vs the fixed-32 loop.
__global__ void k_agg(int layer, int act) {
    int d = blockIdx.x * 8 + (threadIdx.x >> 5);
    if (d >= N_NODES) return;
    int lane = threadIdx.x & 31;
    int beg = g_rowptr[d] + g_boff[d >> 8];
    int end = beg + g_deg[d];
    float hdv = g_hd[d];
    const int2* __restrict__ ed2 = (const int2*)g_edge4;
    const int half_sel = layer >> 1;        // which int2 of the int4
    const bool hi_sel  = (layer & 1) != 0;  // which half of the half2
    float s = 0.0f, acc0 = 0.0f, acc1 = 0.0f;

    for (int base = beg; base < end; base += 32) {
        int p = base + lane;
        bool valid = (p < end);
        int src = 0;
        float pe = 0.0f;
        if (valid) {
            int2 v = ed2[2 * (size_t)p + half_sel];
            src = v.x;
            __half2 hh = *(__half2*)&v.y;
            float etv = hi_sel ? __high2float(hh) : __low2float(hh);
            float alpha = g_hs[src] + hdv + etv;
            alpha = (alpha > 0.0f) ? alpha : 0.2f * alpha;   // leaky_relu 0.2
            pe = __expf(alpha);
        }
        s += pe;
        int nval = end - base; if (nval > 32) nval = 32;
        int nval8 = (nval + 7) & ~7;          // ceil-8, zero-padded
        for (int j0 = 0; j0 < nval8; j0 += 8) {
            #pragma unroll
            for (int jj = 0; jj < 8; jj++) {
                int j = j0 + jj;
                float pj = __shfl_sync(0xffffffffu, pe, j);   // 0 beyond nval
                int   sj = __shfl_sync(0xffffffffu, src, j);
                float2 h = __half22float2(g_hwh[(size_t)sj * 32 + lane]);
                acc0 = fmaf(pj, h.x, acc0);
                acc1 = fmaf(pj, h.y, acc1);
            }
        }
    }
    #pragma unroll
    for (int off = 16; off; off >>= 1)
        s += __shfl_xor_sync(0xffffffffu, s, off);

    float w = 1.0f / (s + 1e-16f);
    size_t o = (size_t)d * C + 2 * lane;
    float2 rv = *(const float2*)&g_res[o];
    float o0 = acc0 * w + rv.x;
    float o1 = acc1 * w + rv.y;
    if (act) {
        o0 = (o0 > 0.0f) ? o0 : 0.01f * o0;
        o1 = (o1 > 0.0f) ? o1 : 0.01f * o1;
    }
    float2 ov; ov.x = o0; ov.y = o1;
    *(float2*)&g_feat[o] = ov;
}

// ---------------- fused pooling + final projection ----------------
__global__ void k_out(const int* __restrict__ batch,
                      const float* __restrict__ Wout, const float* __restrict__ bout,
                      float* __restrict__ out) {
    int g = blockIdx.x;
    int t = threadIdx.x;  // 256 threads
    __shared__ int range[2];
    __shared__ float smx[4][C], ssm[4][C];
    __shared__ float pooled[2 * C];
    if (t == 0) {
        int lo = 0, hi = N_NODES;
        while (lo < hi) { int mid = (lo + hi) >> 1; if (batch[mid] < g) lo = mid + 1; else hi = mid; }
        range[0] = lo;
        lo = range[0]; hi = N_NODES;
        while (lo < hi) { int mid = (lo + hi) >> 1; if (batch[mid] < g + 1) lo = mid + 1; else hi = mid; }
        range[1] = lo;
    }
    __syncthreads();
    int start = range[0], endn = range[1];
    int c = t & 63, q = t >> 6;
    float mx = -CUDART_INF_F, sm = 0.0f;
    for (int n = start + q; n < endn; n += 4) {
        float v = g_feat[(size_t)n * C + c];
        mx = fmaxf(mx, v);
        sm += v;
    }
    smx[q][c] = mx; ssm[q][c] = sm;
    __syncthreads();
    if (t < C) {
        float M = fmaxf(fmaxf(smx[0][t], smx[1][t]), fmaxf(smx[2][t], smx[3][t]));
        float S = ssm[0][t] + ssm[1][t] + ssm[2][t] + ssm[3][t];
        if (!isfinite(M)) M = 0.0f;   // empty graph
        float cnt = (float)(endn - start); if (cnt < 1.0f) cnt = 1.0f;
        float mn = S / cnt;
        pooled[t]     = (M > 0.0f) ? M : 0.01f * M;
        pooled[C + t] = (mn > 0.0f) ? mn : 0.01f * mn;
    }
    __syncthreads();
    float acc = bout[t];
    #pragma unroll
    for (int k = 0; k < 2 * C; k++)
        acc = fmaf(pooled[k], Wout[(size_t)k * D_OUT + t], acc);
    out[(size_t)g * D_OUT + t] = acc;
}

// ---------------- launch (agg0 in profiled slot 4) ------------------------
extern "C" void kernel_launch(void* const* d_in, const int* in_sizes, int n_in,
                              void* d_out, int out_size) {
    const float* x      = (const float*)d_in[0];
    const float* eattr  = (const float*)d_in[1];
    const float* W0     = (const float*)d_in[2];
    const float* asrc0  = (const float*)d_in[3];
    const float* adst0  = (const float*)d_in[4];
    const float* We0    = (const float*)d_in[5];
    const float* ae0    = (const float*)d_in[6];
    const float* Wres0  = (const float*)d_in[7];
    const float* b0     = (const float*)d_in[8];
    const float* W      = (const float*)d_in[9];
    const float* asrc   = (const float*)d_in[10];
    const float* adst   = (const float*)d_in[11];
    const float* We     = (const float*)d_in[12];
    const float* ae     = (const float*)d_in[13];
    const float* Wres   = (const float*)d_in[14];
    const float* b      = (const float*)d_in[15];
    const float* Wout   = (const float*)d_in[16];
    const float* bout   = (const float*)d_in[17];
    const int*   eidx   = (const int*)d_in[18];
    const int*   batch  = (const int*)d_in[19];
    float* out = (float*)d_out;

    const int EB   = (N_EDGES + 255) / 256;
    const int NB8  = (N_NODES + 7) / 8;
    const int NB32 = (N_NODES + 31) / 32;

    k_pre<<<EB, 256>>>(eidx, x, W0, Wres0, asrc0, adst0, b0,     // 1 (hist+aeff+gemm0)
                       We0, ae0, We, ae);
    k_scanA<<<SCAN_BLKS, 256>>>();                               // 2
    k_scatter_et<<<EB, 256>>>(eidx, eattr);                      // 3
    k_agg<<<NB8, 256>>>(0, 1);                                   // 4 <- profiled slot

    // layers 1..3 (F=64), activation after layers 1,2 only
    for (int i = 0; i < 3; i++) {
        k_gemm<C, C, false><<<NB32, 256>>>(nullptr,
                                           W + (size_t)i * C * C,
                                           Wres + (size_t)i * C * C,
                                           asrc + (size_t)i * C,
                                           adst + (size_t)i * C,
                                           b + (size_t)i * C);
        k_agg<<<NB8, 256>>>(i + 1, (i < 2) ? 1 : 0);
    }

    k_out<<<G_GR, D_OUT>>>(batch, Wout, bout, out);
}